// round 4
// baseline (speedup 1.0000x reference)
#include <cuda_runtime.h>
#include <math.h>

// Problem constants
#define NN 2
#define DD 160
#define HH 192
#define WW 192
#define TILE 32
#define HALO 36          // TILE + 4
#define CHUNK 20         // D-slices of output per block
#define NCHUNK 8         // DD / CHUNK
#define VWIN 125.0f
#define EPSV 1e-5f

__device__ double g_acc;

__global__ void ncc_reset_kernel() { g_acc = 0.0; }

__global__ void ncc_finalize_kernel(float* out) {
    const double total = (double)NN * DD * HH * WW;
    out[0] = (float)(-g_acc / total);
}

__global__ __launch_bounds__(1024, 1)
void ncc_main_kernel(const float* __restrict__ I, const float* __restrict__ J) {
    __shared__ float2 sIJ[HALO][HALO];      // staged I,J slice (halo region)
    __shared__ float4 rs4[HALO][TILE];      // W-summed fields: I, J, I2, J2
    __shared__ float  rs1[HALO][TILE];      // W-summed field: IJ
    __shared__ float  redbuf[32];

    const int tx = threadIdx.x;
    const int ty = threadIdx.y;
    const int tid = ty * 32 + tx;
    const int w0 = blockIdx.x * TILE;
    const int h0 = blockIdx.y * TILE;
    const int n  = blockIdx.z / NCHUNK;
    const int z0 = (blockIdx.z % NCHUNK) * CHUNK;

    const size_t nbase = (size_t)n * DD * HH * WW;
    const float* Ibase = I + nbase;
    const float* Jbase = J + nbase;

    // 5-deep ring of per-slice 2D window sums for the 5 fields
    float rA0=0.f,rA1=0.f,rA2=0.f,rA3=0.f,rA4=0.f;   // sum I
    float rB0=0.f,rB1=0.f,rB2=0.f,rB3=0.f,rB4=0.f;   // sum J
    float rC0=0.f,rC1=0.f,rC2=0.f,rC3=0.f,rC4=0.f;   // sum I^2
    float rD0=0.f,rD1=0.f,rD2=0.f,rD3=0.f,rD4=0.f;   // sum J^2
    float rE0=0.f,rE1=0.f,rE2=0.f,rE3=0.f,rE4=0.f;   // sum I*J

    float local_cc = 0.f;

    for (int z = z0 - 2; z <= z0 + CHUNK + 1; ++z) {
        float sA = 0.f, sB = 0.f, sC = 0.f, sD = 0.f, sE = 0.f;

        if (z >= 0 && z < DD) {
            const float* Islice = Ibase + (size_t)z * HH * WW;
            const float* Jslice = Jbase + (size_t)z * HH * WW;

            // --- stage I,J halo slice into shared (zero-padded) ---
            #pragma unroll
            for (int base = 0; base < HALO * HALO; base += 1024) {
                int idx = base + tid;
                if (idx < HALO * HALO) {
                    int hh = idx / HALO;
                    int ww = idx - hh * HALO;
                    int gh = h0 - 2 + hh;
                    int gw = w0 - 2 + ww;
                    float2 v = make_float2(0.f, 0.f);
                    if (gh >= 0 && gh < HH && gw >= 0 && gw < WW) {
                        size_t off = (size_t)gh * WW + gw;
                        v.x = Islice[off];
                        v.y = Jslice[off];
                    }
                    sIJ[hh][ww] = v;
                }
            }
            __syncthreads();

            // --- W-direction 5-tap sums of the 5 fields ---
            #pragma unroll
            for (int base = 0; base < HALO * TILE; base += 1024) {
                int idx = base + tid;
                if (idx < HALO * TILE) {
                    int hh = idx >> 5;          // / TILE
                    int w  = idx & 31;          // % TILE
                    float a = 0.f, b = 0.f, c = 0.f, d = 0.f, e = 0.f;
                    #pragma unroll
                    for (int dw = 0; dw < 5; ++dw) {
                        float2 v = sIJ[hh][w + dw];
                        a += v.x;
                        b += v.y;
                        c = fmaf(v.x, v.x, c);
                        d = fmaf(v.y, v.y, d);
                        e = fmaf(v.x, v.y, e);
                    }
                    rs4[hh][w] = make_float4(a, b, c, d);
                    rs1[hh][w] = e;
                }
            }
            __syncthreads();

            // --- H-direction 5-tap sums -> 2D slice sums at (ty,tx) ---
            #pragma unroll
            for (int dh = 0; dh < 5; ++dh) {
                float4 r = rs4[ty + dh][tx];
                sA += r.x; sB += r.y; sC += r.z; sD += r.w;
                sE += rs1[ty + dh][tx];
            }
            // NOTE: no extra sync needed here — the sync after the next
            // iteration's staging separates these rs reads from its rs writes.
        }

        // --- push into D ring ---
        rA0=rA1; rA1=rA2; rA2=rA3; rA3=rA4; rA4=sA;
        rB0=rB1; rB1=rB2; rB2=rB3; rB3=rB4; rB4=sB;
        rC0=rC1; rC1=rC2; rC2=rC3; rC3=rC4; rC4=sC;
        rD0=rD1; rD1=rD2; rD2=rD3; rD3=rD4; rD4=sD;
        rE0=rE1; rE1=rE2; rE2=rE3; rE3=rE4; rE4=sE;

        // --- emit cc for z_out = z - 2 ---
        if (z >= z0 + 2) {
            float a = rA0 + rA1 + rA2 + rA3 + rA4;   // I_sum
            float b = rB0 + rB1 + rB2 + rB3 + rB4;   // J_sum
            float c = rC0 + rC1 + rC2 + rC3 + rC4;   // I2_sum
            float d = rD0 + rD1 + rD2 + rD3 + rD4;   // J2_sum
            float e = rE0 + rE1 + rE2 + rE3 + rE4;   // IJ_sum

            const float invV = 1.0f / VWIN;
            float cross = fmaf(-(a * invV), b, e);   // e - a*b/V
            float Ivar  = fmaf(-(a * invV), a, c);   // c - a*a/V
            float Jvar  = fmaf(-(b * invV), b, d);   // d - b*b/V
            float denom = fmaf(Ivar, Jvar, EPSV);
            float cc = __fdividef(cross * cross, denom);
            local_cc += cc;
        }
    }

    // --- block reduction ---
    float v = local_cc;
    #pragma unroll
    for (int off = 16; off > 0; off >>= 1)
        v += __shfl_xor_sync(0xFFFFFFFFu, v, off);
    if ((tid & 31) == 0) redbuf[tid >> 5] = v;
    __syncthreads();
    if (tid < 32) {
        float w = redbuf[tid];
        #pragma unroll
        for (int off = 16; off > 0; off >>= 1)
            w += __shfl_xor_sync(0xFFFFFFFFu, w, off);
        if (tid == 0) atomicAdd(&g_acc, (double)w);
    }
}

extern "C" void kernel_launch(void* const* d_in, const int* in_sizes, int n_in,
                              void* d_out, int out_size) {
    const float* I = (const float*)d_in[0];
    const float* J = (const float*)d_in[1];
    float* out = (float*)d_out;

    ncc_reset_kernel<<<1, 1>>>();

    dim3 block(32, 32);
    dim3 grid(WW / TILE, HH / TILE, NN * NCHUNK);   // 6 x 6 x 16 = 576 blocks
    ncc_main_kernel<<<grid, block>>>(I, J);

    ncc_finalize_kernel<<<1, 1>>>(out);
}

// round 5
// speedup vs baseline: 1.8510x; 1.8510x over previous
#include <cuda_runtime.h>

// Problem constants
#define NN 2
#define DD 160
#define HH 192
#define WW 192
#define HW (HH * WW)

#define TILE_W 32
#define TILE_H 16
#define HALO_W 36          // TILE_W + 4
#define HALO_H 20          // TILE_H + 4
#define SROW 38            // padded float2 row stride for sIJ (bank + 16B align)
#define RROW 33            // padded row stride for rs4/rs1
#define CHUNK 80           // D-slices of output per block
#define NCHUNK 2           // DD / CHUNK
#define NITER (CHUNK + 5)  // 85 pipeline iterations
#define NTHREADS 512
#define STAGE_ELEMS (HALO_H * HALO_W)   // 720
#define WTASKS (8 * HALO_H)             // 160 W-pass tasks

#define VINV (1.0f / 125.0f)
#define EPSV 1e-5f

__device__ double g_acc;

__global__ void ncc_reset_kernel() { g_acc = 0.0; }

__global__ void ncc_finalize_kernel(float* out) {
    out[0] = (float)(-g_acc / ((double)NN * DD * HH * WW));
}

__global__ __launch_bounds__(NTHREADS, 1)
void ncc_main_kernel(const float* __restrict__ I, const float* __restrict__ J) {
    __shared__ alignas(16) float2 sIJ[2][HALO_H][SROW];  // double-buffered halo slice
    __shared__ float4 rs4[HALO_H][RROW];                 // W-summed I, J, I2, J2
    __shared__ float  rs1[HALO_H][RROW];                 // W-summed IJ
    __shared__ float  redbuf[16];

    const int tid = threadIdx.x;
    const int tx = tid & 31;
    const int ty = tid >> 5;                 // 0..15
    const int w0b = blockIdx.x * TILE_W;
    const int h0b = blockIdx.y * TILE_H;
    const int n   = blockIdx.z >> 1;
    const int z0  = (blockIdx.z & 1) * CHUNK;

    const float* __restrict__ Ibase = I + (size_t)n * DD * HW;
    const float* __restrict__ Jbase = J + (size_t)n * DD * HW;

    // ---- precompute staging element mapping (z-invariant) ----
    int off0, st0, off1 = 0, st1 = 0;
    {
        int e = tid;
        int hh = e / HALO_W, ww = e - hh * HALO_W;
        int gh = h0b - 2 + hh, gw = w0b - 2 + ww;
        off0 = (gh >= 0 && gh < HH && gw >= 0 && gw < WW) ? gh * WW + gw : -1;
        st0 = hh * SROW + ww;
        e = tid + NTHREADS;
        if (e < STAGE_ELEMS) {
            hh = e / HALO_W; ww = e - hh * HALO_W;
            gh = h0b - 2 + hh; gw = w0b - 2 + ww;
            off1 = (gh >= 0 && gh < HH && gw >= 0 && gw < WW) ? gh * WW + gw : -1;
            st1 = hh * SROW + ww;
        }
    }
    const bool has2 = (tid + NTHREADS) < STAGE_ELEMS;

    // ---- precompute W-pass task mapping ----
    const bool wact = tid < WTASKS;
    const int whh = tid % HALO_H;            // row 0..19
    const int wwg = tid / HALO_H;            // w-group 0..7
    const int wsoff = whh * SROW + wwg * 4;  // float2 offset into a sIJ buffer

    // ---- pipeline state ----
    float rA[5] = {0,0,0,0,0}, rB[5] = {0,0,0,0,0}, rC[5] = {0,0,0,0,0};
    float rD[5] = {0,0,0,0,0}, rE[5] = {0,0,0,0,0};
    float tA = 0.f, tB = 0.f, tC = 0.f, tD = 0.f, tE = 0.f;
    float local_cc = 0.f;
    float2 p0, p1;

    // prefetch helper inlined manually below via macro-ish lambdas
    auto prefetch = [&](int z) {
        p0 = make_float2(0.f, 0.f);
        p1 = make_float2(0.f, 0.f);
        if ((unsigned)z < (unsigned)DD) {
            const float* pi = Ibase + (size_t)z * HW;
            const float* pj = Jbase + (size_t)z * HW;
            if (off0 >= 0) { p0.x = __ldg(pi + off0); p0.y = __ldg(pj + off0); }
            if (has2 && off1 >= 0) { p1.x = __ldg(pi + off1); p1.y = __ldg(pj + off1); }
        }
    };
    auto stage_store = [&](int buf) {
        float2* b = &sIJ[buf][0][0];
        b[st0] = p0;
        if (has2) b[st1] = p1;
    };

    // prologue: slice z0-2 into buffer 0; slice z0-1 held in registers
    prefetch(z0 - 2);
    stage_store(0);
    prefetch(z0 - 1);

    int cur = 0;
    for (int g = 0; g < NITER / 5; ++g) {
        #pragma unroll
        for (int k = 0; k < 5; ++k) {
            const int i = g * 5 + k;

            __syncthreads();   // sIJ[cur] staged; rs free (prev H-pass done)

            // ---- W-pass: 5-tap sums along W for 5 fields (sliding, groups of 4) ----
            if (wact) {
                const float2* bp = &sIJ[cur][0][0] + wsoff;
                const float4* rp4 = reinterpret_cast<const float4*>(bp);
                float4 q0 = rp4[0], q1 = rp4[1], q2 = rp4[2], q3 = rp4[3];
                float x0 = q0.x, y0 = q0.y, x1 = q0.z, y1 = q0.w;
                float x2 = q1.x, y2 = q1.y, x3 = q1.z, y3 = q1.w;
                float x4 = q2.x, y4 = q2.y, x5 = q2.z, y5 = q2.w;
                float x6 = q3.x, y6 = q3.y, x7 = q3.z, y7 = q3.w;

                float a = x0 + x1 + x2 + x3 + x4;
                float b = y0 + y1 + y2 + y3 + y4;
                float c = x0*x0; c = fmaf(x1,x1,c); c = fmaf(x2,x2,c); c = fmaf(x3,x3,c); c = fmaf(x4,x4,c);
                float d = y0*y0; d = fmaf(y1,y1,d); d = fmaf(y2,y2,d); d = fmaf(y3,y3,d); d = fmaf(y4,y4,d);
                float e = x0*y0; e = fmaf(x1,y1,e); e = fmaf(x2,y2,e); e = fmaf(x3,y3,e); e = fmaf(x4,y4,e);

                float4* d4 = &rs4[whh][wwg * 4];
                float*  d1 = &rs1[whh][wwg * 4];
                d4[0] = make_float4(a, b, c, d); d1[0] = e;

                // slide +1: drop x0, add x5
                a += x5 - x0; b += y5 - y0;
                c += fmaf(x5, x5, -(x0 * x0));
                d += fmaf(y5, y5, -(y0 * y0));
                e += fmaf(x5, y5, -(x0 * y0));
                d4[1] = make_float4(a, b, c, d); d1[1] = e;

                a += x6 - x1; b += y6 - y1;
                c += fmaf(x6, x6, -(x1 * x1));
                d += fmaf(y6, y6, -(y1 * y1));
                e += fmaf(x6, y6, -(x1 * y1));
                d4[2] = make_float4(a, b, c, d); d1[2] = e;

                a += x7 - x2; b += y7 - y2;
                c += fmaf(x7, x7, -(x2 * x2));
                d += fmaf(y7, y7, -(y2 * y2));
                e += fmaf(x7, y7, -(x2 * y2));
                d4[3] = make_float4(a, b, c, d); d1[3] = e;
            }

            __syncthreads();   // rs ready

            // store prefetched slice (s+1) into the other buffer, then issue
            // gmem loads for slice s+2 — consumed one full iteration later.
            stage_store(cur ^ 1);
            prefetch(z0 + i);   // z0 + i == s + 2

            // ---- H-pass: 5-tap sums along H -> 2D slice sums at (ty,tx) ----
            float sA = 0.f, sB = 0.f, sC = 0.f, sD = 0.f, sE = 0.f;
            #pragma unroll
            for (int dh = 0; dh < 5; ++dh) {
                float4 r = rs4[ty + dh][tx];
                sA += r.x; sB += r.y; sC += r.z; sD += r.w;
                sE += rs1[ty + dh][tx];
            }

            // ---- D running box-sum (ring slot k is the slice from 5 iters ago) ----
            tA += sA - rA[k]; rA[k] = sA;
            tB += sB - rB[k]; rB[k] = sB;
            tC += sC - rC[k]; rC[k] = sC;
            tD += sD - rD[k]; rD[k] = sD;
            tE += sE - rE[k]; rE[k] = sE;

            // ---- emit cc for output slice s-2 ----
            if (i >= 4 && i < NITER - 1) {
                float ai = tA * VINV;
                float bi = tB * VINV;
                float cross = fmaf(-ai, tB, tE);
                float Ivar  = fmaf(-ai, tA, tC);
                float Jvar  = fmaf(-bi, tB, tD);
                local_cc += __fdividef(cross * cross, fmaf(Ivar, Jvar, EPSV));
            }

            cur ^= 1;
        }
    }

    // ---- block reduction ----
    float v = local_cc;
    #pragma unroll
    for (int off = 16; off > 0; off >>= 1)
        v += __shfl_xor_sync(0xFFFFFFFFu, v, off);
    if (tx == 0) redbuf[ty] = v;
    __syncthreads();
    if (tid < 16) {
        float w = redbuf[tid];
        #pragma unroll
        for (int off = 8; off > 0; off >>= 1)
            w += __shfl_xor_sync(0xFFFFu, w, off);
        if (tid == 0) atomicAdd(&g_acc, (double)w);
    }
}

extern "C" void kernel_launch(void* const* d_in, const int* in_sizes, int n_in,
                              void* d_out, int out_size) {
    const float* I = (const float*)d_in[0];
    const float* J = (const float*)d_in[1];
    float* out = (float*)d_out;

    ncc_reset_kernel<<<1, 1>>>();

    dim3 block(NTHREADS);
    dim3 grid(WW / TILE_W, HH / TILE_H, NN * NCHUNK);   // 6 x 12 x 4 = 288 blocks
    ncc_main_kernel<<<grid, block>>>(I, J);

    ncc_finalize_kernel<<<1, 1>>>(out);
}

// round 6
// speedup vs baseline: 2.3473x; 1.2682x over previous
#include <cuda_runtime.h>

// Problem constants
#define NN 2
#define DD 160
#define HH 192
#define WW 192
#define HW (HH * WW)

#define TILE_W 32
#define TILE_H 16          // per CTA; 2 rows per thread
#define HALO_W 36
#define HALO_H 20
#define SROW 38            // padded float2 row stride for sIJ (304 B, 16B-aligned)
#define RROW 33            // padded float4/float row stride for rs
#define CHUNK 80
#define NCHUNK 2
#define NITER (CHUNK + 5)  // 85 = 17 * 5
#define NTHREADS 256
#define STAGE_ELEMS (HALO_H * HALO_W)   // 720 -> 3 per thread
#define WTASKS (8 * HALO_H)             // 160 sliding W-tasks

#define VINV (1.0f / 125.0f)
#define EPSV 1e-5f

__device__ double g_acc;

__global__ void ncc_reset_kernel() { g_acc = 0.0; }

__global__ void ncc_finalize_kernel(float* out) {
    out[0] = (float)(-g_acc / ((double)NN * DD * HH * WW));
}

__global__ __launch_bounds__(NTHREADS, 2)
void ncc_main_kernel(const float* __restrict__ I, const float* __restrict__ J) {
    __shared__ alignas(16) float2 sIJ[2][HALO_H][SROW];  // double-buffered halo slice
    __shared__ alignas(16) float4 rs4[HALO_H][RROW];     // W-sums: I, J, I2, J2 (swizzled cols)
    __shared__ float  rs1[HALO_H][RROW];                 // W-sums: IJ (swizzled cols)
    __shared__ float  redbuf[8];

    const int tid = threadIdx.x;
    const int tx = tid & 31;
    const int ty = tid >> 5;                 // 0..7 -> output rows 2ty, 2ty+1
    const int w0b = blockIdx.x * TILE_W;
    const int h0b = blockIdx.y * TILE_H;
    const int n   = blockIdx.z >> 1;
    const int z0  = (blockIdx.z & 1) * CHUNK;

    const float* __restrict__ Ibase = I + (size_t)n * DD * HW;
    const float* __restrict__ Jbase = J + (size_t)n * DD * HW;

    // ---- staging mapping: 3 elements per thread (720 total) ----
    int goff[3], soff[3];
    #pragma unroll
    for (int t = 0; t < 3; ++t) {
        int e = tid + t * NTHREADS;
        if (e < STAGE_ELEMS) {
            int hh = e / HALO_W, ww = e - hh * HALO_W;
            int gh = h0b - 2 + hh, gw = w0b - 2 + ww;
            goff[t] = (gh >= 0 && gh < HH && gw >= 0 && gw < WW) ? gh * WW + gw : -1;
            soff[t] = hh * SROW + ww;
        } else { goff[t] = -1; soff[t] = -2; }
    }

    // ---- W-pass task mapping (tid < 160): row whh, w-group wwg (4 outputs) ----
    const bool wact = tid < WTASKS;
    const int wwg = tid & 7;
    const int whh = tid >> 3;
    const int wsoff = whh * SROW + wwg * 4;       // float2 units
    // swizzled store columns: col(j) = 8j + (wwg ^ 2j)
    const int c0 = wwg;
    const int c1 = 8  + (wwg ^ 2);
    const int c2 = 16 + (wwg ^ 4);
    const int c3 = 24 + (wwg ^ 6);

    // ---- H-pass read column (inverse swizzle of logical w = tx) ----
    const int swc = 8 * (tx & 3) + ((tx >> 2) ^ (2 * (tx & 3)));

    // ---- pipeline state: 2 output rows per thread ----
    float rA[2][5] = {{0}}, rB[2][5] = {{0}}, rC[2][5] = {{0}},
          rD[2][5] = {{0}}, rE[2][5] = {{0}};
    float tA[2] = {0,0}, tB[2] = {0,0}, tC[2] = {0,0}, tD[2] = {0,0}, tE[2] = {0,0};
    float local_cc = 0.f;
    float2 p0, p1, p2;

    auto prefetch = [&](int z) {
        p0 = make_float2(0.f, 0.f);
        p1 = make_float2(0.f, 0.f);
        p2 = make_float2(0.f, 0.f);
        if ((unsigned)z < (unsigned)DD) {
            const float* pi = Ibase + (size_t)z * HW;
            const float* pj = Jbase + (size_t)z * HW;
            if (goff[0] >= 0) { p0.x = __ldg(pi + goff[0]); p0.y = __ldg(pj + goff[0]); }
            if (goff[1] >= 0) { p1.x = __ldg(pi + goff[1]); p1.y = __ldg(pj + goff[1]); }
            if (goff[2] >= 0) { p2.x = __ldg(pi + goff[2]); p2.y = __ldg(pj + goff[2]); }
        }
    };
    auto stage_store = [&](int buf) {
        float2* b = &sIJ[buf][0][0];
        b[soff[0]] = p0;
        if (soff[1] >= 0) b[soff[1]] = p1;
        if (soff[2] >= 0) b[soff[2]] = p2;
    };

    // prologue: slice z0-2 staged into buffer 0; slice z0-1 held in registers
    prefetch(z0 - 2);
    stage_store(0);
    prefetch(z0 - 1);

    int cur = 0;
    for (int g = 0; g < NITER / 5; ++g) {
        #pragma unroll
        for (int k = 0; k < 5; ++k) {
            const int i = g * 5 + k;

            __syncthreads();   // sIJ[cur] staged; rs free (prev H-pass done)

            // ---- W-pass: sliding 5-tap W sums, 4 outputs per task ----
            if (wact) {
                const float4* rp4 = reinterpret_cast<const float4*>(&sIJ[cur][0][0] + wsoff);
                float4 q0 = rp4[0], q1 = rp4[1], q2 = rp4[2], q3 = rp4[3];
                float x0 = q0.x, y0 = q0.y, x1 = q0.z, y1 = q0.w;
                float x2 = q1.x, y2 = q1.y, x3 = q1.z, y3 = q1.w;
                float x4 = q2.x, y4 = q2.y, x5 = q2.z, y5 = q2.w;
                float x6 = q3.x, y6 = q3.y, x7 = q3.z, y7 = q3.w;

                float a = x0 + x1 + x2 + x3 + x4;
                float b = y0 + y1 + y2 + y3 + y4;
                float c = x0*x0; c = fmaf(x1,x1,c); c = fmaf(x2,x2,c); c = fmaf(x3,x3,c); c = fmaf(x4,x4,c);
                float d = y0*y0; d = fmaf(y1,y1,d); d = fmaf(y2,y2,d); d = fmaf(y3,y3,d); d = fmaf(y4,y4,d);
                float e = x0*y0; e = fmaf(x1,y1,e); e = fmaf(x2,y2,e); e = fmaf(x3,y3,e); e = fmaf(x4,y4,e);

                rs4[whh][c0] = make_float4(a, b, c, d); rs1[whh][c0] = e;

                a += x5 - x0; b += y5 - y0;
                c += fmaf(x5, x5, -(x0 * x0));
                d += fmaf(y5, y5, -(y0 * y0));
                e += fmaf(x5, y5, -(x0 * y0));
                rs4[whh][c1] = make_float4(a, b, c, d); rs1[whh][c1] = e;

                a += x6 - x1; b += y6 - y1;
                c += fmaf(x6, x6, -(x1 * x1));
                d += fmaf(y6, y6, -(y1 * y1));
                e += fmaf(x6, y6, -(x1 * y1));
                rs4[whh][c2] = make_float4(a, b, c, d); rs1[whh][c2] = e;

                a += x7 - x2; b += y7 - y2;
                c += fmaf(x7, x7, -(x2 * x2));
                d += fmaf(y7, y7, -(y2 * y2));
                e += fmaf(x7, y7, -(x2 * y2));
                rs4[whh][c3] = make_float4(a, b, c, d); rs1[whh][c3] = e;
            }

            __syncthreads();   // rs ready

            // stage slice s+1 into the other buffer, then issue loads for s+2
            stage_store(cur ^ 1);
            prefetch(z0 + i);

            // ---- H-pass: 2 output rows per thread, 6 shared row reads ----
            {
                const int r0 = 2 * ty;
                float4 q0 = rs4[r0 + 0][swc]; float e0 = rs1[r0 + 0][swc];
                float4 q1 = rs4[r0 + 1][swc]; float e1 = rs1[r0 + 1][swc];
                float4 q2 = rs4[r0 + 2][swc]; float e2 = rs1[r0 + 2][swc];
                float4 q3 = rs4[r0 + 3][swc]; float e3 = rs1[r0 + 3][swc];
                float4 q4 = rs4[r0 + 4][swc]; float e4 = rs1[r0 + 4][swc];
                float4 q5 = rs4[r0 + 5][swc]; float e5 = rs1[r0 + 5][swc];

                // shared middle: rows 1..4
                float mA = q1.x + q2.x + q3.x + q4.x;
                float mB = q1.y + q2.y + q3.y + q4.y;
                float mC = q1.z + q2.z + q3.z + q4.z;
                float mD = q1.w + q2.w + q3.w + q4.w;
                float mE = e1 + e2 + e3 + e4;

                float sA0 = mA + q0.x, sA1 = mA + q5.x;
                float sB0 = mB + q0.y, sB1 = mB + q5.y;
                float sC0 = mC + q0.z, sC1 = mC + q5.z;
                float sD0 = mD + q0.w, sD1 = mD + q5.w;
                float sE0 = mE + e0,   sE1 = mE + e5;

                // ---- D running box-sums (ring slot k = slice 5 iters ago) ----
                tA[0] += sA0 - rA[0][k]; rA[0][k] = sA0;
                tB[0] += sB0 - rB[0][k]; rB[0][k] = sB0;
                tC[0] += sC0 - rC[0][k]; rC[0][k] = sC0;
                tD[0] += sD0 - rD[0][k]; rD[0][k] = sD0;
                tE[0] += sE0 - rE[0][k]; rE[0][k] = sE0;

                tA[1] += sA1 - rA[1][k]; rA[1][k] = sA1;
                tB[1] += sB1 - rB[1][k]; rB[1][k] = sB1;
                tC[1] += sC1 - rC[1][k]; rC[1][k] = sC1;
                tD[1] += sD1 - rD[1][k]; rD[1][k] = sD1;
                tE[1] += sE1 - rE[1][k]; rE[1][k] = sE1;
            }

            // ---- emit cc for output slice s-2 (both rows) ----
            if (i >= 4 && i < NITER - 1) {
                #pragma unroll
                for (int r = 0; r < 2; ++r) {
                    float ai = tA[r] * VINV;
                    float bi = tB[r] * VINV;
                    float cross = fmaf(-ai, tB[r], tE[r]);
                    float Ivar  = fmaf(-ai, tA[r], tC[r]);
                    float Jvar  = fmaf(-bi, tB[r], tD[r]);
                    local_cc += __fdividef(cross * cross, fmaf(Ivar, Jvar, EPSV));
                }
            }

            cur ^= 1;
        }
    }

    // ---- block reduction ----
    float v = local_cc;
    #pragma unroll
    for (int off = 16; off > 0; off >>= 1)
        v += __shfl_xor_sync(0xFFFFFFFFu, v, off);
    if (tx == 0) redbuf[ty] = v;
    __syncthreads();
    if (tid < 8) {
        float w = redbuf[tid];
        #pragma unroll
        for (int off = 4; off > 0; off >>= 1)
            w += __shfl_xor_sync(0xFFu, w, off);
        if (tid == 0) atomicAdd(&g_acc, (double)w);
    }
}

extern "C" void kernel_launch(void* const* d_in, const int* in_sizes, int n_in,
                              void* d_out, int out_size) {
    const float* I = (const float*)d_in[0];
    const float* J = (const float*)d_in[1];
    float* out = (float*)d_out;

    ncc_reset_kernel<<<1, 1>>>();

    dim3 block(NTHREADS);
    dim3 grid(WW / TILE_W, HH / TILE_H, NN * NCHUNK);   // 6 x 12 x 4 = 288 blocks, 1 wave @ occ 2
    ncc_main_kernel<<<grid, block>>>(I, J);

    ncc_finalize_kernel<<<1, 1>>>(out);
}

// round 9
// speedup vs baseline: 2.4574x; 1.0469x over previous
#include <cuda_runtime.h>

// Problem constants
#define NN 2
#define DD 160
#define HH 192
#define WW 192
#define HW (HH * WW)

#define TILE_W 32
#define TILE_H 16          // per CTA; 2 output rows per thread
#define HALO_W 36
#define HALO_H 20
#define SROW 38            // padded float2 row stride for sIJ
#define RROW 33            // padded row stride for rs
#define CHUNK 80
#define NITER (CHUNK + 5)  // 85 = 17 * 5
#define NTHREADS 256
#define STAGE_ELEMS (HALO_H * HALO_W)   // 720 -> 3 per thread
#define WTASKS 160                      // 20 rows x 8 groups of 4 outputs

#define VINV (1.0f / 125.0f)
#define EPSV 1e-5f

typedef unsigned long long ull;

// ---- packed f32x2 helpers (sm_103a FFMA2 path; ptxas never auto-fuses) ----
__device__ __forceinline__ ull pk2(float lo, float hi) {
    ull r; asm("mov.b64 %0, {%1, %2};" : "=l"(r) : "f"(lo), "f"(hi)); return r;
}
__device__ __forceinline__ void upk2(ull v, float& lo, float& hi) {
    asm("mov.b64 {%0, %1}, %2;" : "=f"(lo), "=f"(hi) : "l"(v));
}
__device__ __forceinline__ ull fadd2(ull a, ull b) {
    ull r; asm("add.rn.f32x2 %0, %1, %2;" : "=l"(r) : "l"(a), "l"(b)); return r;
}
__device__ __forceinline__ ull fmul2(ull a, ull b) {
    ull r; asm("mul.rn.f32x2 %0, %1, %2;" : "=l"(r) : "l"(a), "l"(b)); return r;
}
__device__ __forceinline__ ull ffma2(ull a, ull b, ull c) {
    ull r; asm("fma.rn.f32x2 %0, %1, %2, %3;" : "=l"(r) : "l"(a), "l"(b), "l"(c)); return r;
}

__device__ double g_acc;   // static-init 0; finalize re-zeroes for graph replay

__global__ void ncc_finalize_kernel(float* out) {
    out[0] = (float)(-g_acc / ((double)NN * DD * HH * WW));
    g_acc = 0.0;           // deterministic across replays
}

__global__ __launch_bounds__(NTHREADS, 2)
void ncc_main_kernel(const float* __restrict__ I, const float* __restrict__ J) {
    __shared__ alignas(16) float2 sIJ[2][HALO_H][SROW];   // double-buffered halo slice
    __shared__ alignas(16) float4 rs4[2][HALO_H][RROW];   // double-buffered W-sums (A,B,C,D)
    __shared__ float  rs1[2][HALO_H][RROW];               // double-buffered W-sums (E)
    __shared__ float  redbuf[8];

    const int tid = threadIdx.x;
    const int tx = tid & 31;
    const int ty = tid >> 5;                 // 0..7 -> output rows 2ty, 2ty+1
    const int w0b = blockIdx.x * TILE_W;
    const int h0b = blockIdx.y * TILE_H;
    const int n   = blockIdx.z >> 1;
    const int z0  = (blockIdx.z & 1) * CHUNK;

    const float* __restrict__ Ibase = I + (size_t)n * DD * HW;
    const float* __restrict__ Jbase = J + (size_t)n * DD * HW;

    const ull NG = 0xBF800000BF800000ULL;    // packed (-1.0f, -1.0f)

    // ---- staging mapping: 3 elements per thread ----
    int goff[3], soff[3];
    #pragma unroll
    for (int t = 0; t < 3; ++t) {
        int e = tid + t * NTHREADS;
        if (e < STAGE_ELEMS) {
            int hh = e / HALO_W, ww = e - hh * HALO_W;
            int gh = h0b - 2 + hh, gw = w0b - 2 + ww;
            goff[t] = (gh >= 0 && gh < HH && gw >= 0 && gw < WW) ? gh * WW + gw : -1;
            soff[t] = hh * SROW + ww;
        } else { goff[t] = -1; soff[t] = -2; }
    }

    // ---- W-pass task mapping (tid < 160) ----
    const bool wact = tid < WTASKS;
    const int wwg = tid & 7;
    const int whh = tid >> 3;
    const int wsoff = whh * SROW + wwg * 4;       // float2 units
    const int c0 = wwg;
    const int c1 = 8  + (wwg ^ 2);
    const int c2 = 16 + (wwg ^ 4);
    const int c3 = 24 + (wwg ^ 6);

    // ---- H-pass read column (inverse swizzle of logical w = tx) ----
    const int swc = 8 * (tx & 3) + ((tx >> 2) ^ (2 * (tx & 3)));

    // ---- pipeline state ----
    ull rAB[2][5] = {{0,0,0,0,0},{0,0,0,0,0}};
    ull rCD[2][5] = {{0,0,0,0,0},{0,0,0,0,0}};
    float rE[2][5] = {{0,0,0,0,0},{0,0,0,0,0}};
    ull tAB[2] = {0, 0}, tCD[2] = {0, 0};
    float tE[2] = {0.f, 0.f};
    float local_cc = 0.f;
    float2 p0, p1, p2;

    auto prefetch = [&](int z) {
        p0 = make_float2(0.f, 0.f);
        p1 = make_float2(0.f, 0.f);
        p2 = make_float2(0.f, 0.f);
        if ((unsigned)z < (unsigned)DD) {
            const float* pi = Ibase + (size_t)z * HW;
            const float* pj = Jbase + (size_t)z * HW;
            if (goff[0] >= 0) { p0.x = __ldg(pi + goff[0]); p0.y = __ldg(pj + goff[0]); }
            if (goff[1] >= 0) { p1.x = __ldg(pi + goff[1]); p1.y = __ldg(pj + goff[1]); }
            if (goff[2] >= 0) { p2.x = __ldg(pi + goff[2]); p2.y = __ldg(pj + goff[2]); }
        }
    };
    auto stage_store = [&](int buf) {
        float2* b = &sIJ[buf][0][0];
        b[soff[0]] = p0;
        if (soff[1] >= 0) b[soff[1]] = p1;
        if (soff[2] >= 0) b[soff[2]] = p2;
    };

    // prologue: slice z0-2 into sIJ[0]; slice z0-1 prefetched (stored at i=0)
    prefetch(z0 - 2);
    stage_store(0);
    prefetch(z0 - 1);

    for (int g = 0; g < NITER / 5; ++g) {
        #pragma unroll
        for (int k = 0; k < 5; ++k) {
            const int i = g * 5 + k;
            const int pb = i & 1;        // W reads sIJ[pb], writes rs[pb]
            const int qb = pb ^ 1;       // stage writes sIJ[qb], H reads rs[qb]

            __syncthreads();   // ONE barrier per slice

            // ---- stage slice s+1 (prefetched last iter) into the other buffer ----
            stage_store(qb);

            // ---- issue gmem loads for slice s+2 (consumed next iteration) ----
            prefetch((i <= CHUNK + 1) ? (z0 + i) : -1);

            // ---- W-pass on slice s (packed f32x2) ----
            if (wact && i <= CHUNK + 3) {
                const float4* rp4 = reinterpret_cast<const float4*>(&sIJ[pb][0][0] + wsoff);
                float4 q0 = rp4[0], q1 = rp4[1], q2 = rp4[2], q3 = rp4[3];
                ull v0 = pk2(q0.x, q0.y), v1 = pk2(q0.z, q0.w);
                ull v2 = pk2(q1.x, q1.y), v3 = pk2(q1.z, q1.w);
                ull v4 = pk2(q2.x, q2.y), v5 = pk2(q2.z, q2.w);
                ull v6 = pk2(q3.x, q3.y), v7 = pk2(q3.z, q3.w);

                ull ab = fadd2(fadd2(fadd2(v0, v1), fadd2(v2, v3)), v4);
                ull cd = fmul2(v0, v0);
                cd = ffma2(v1, v1, cd); cd = ffma2(v2, v2, cd);
                cd = ffma2(v3, v3, cd); cd = ffma2(v4, v4, cd);
                float e = q0.x * q0.y;
                e = fmaf(q0.z, q0.w, e); e = fmaf(q1.x, q1.y, e);
                e = fmaf(q1.z, q1.w, e); e = fmaf(q2.x, q2.y, e);

                float fa, fb, fc, fd;
                upk2(ab, fa, fb); upk2(cd, fc, fd);
                rs4[pb][whh][c0] = make_float4(fa, fb, fc, fd); rs1[pb][whh][c0] = e;

                // slide +1: drop v0, add v5
                ab = fadd2(ab, v5); ab = ffma2(v0, NG, ab);
                { ull nv = fmul2(v0, NG); cd = ffma2(v5, v5, cd); cd = ffma2(nv, v0, cd); }
                e = fmaf(q2.z, q2.w, e); e = fmaf(-q0.x, q0.y, e);
                upk2(ab, fa, fb); upk2(cd, fc, fd);
                rs4[pb][whh][c1] = make_float4(fa, fb, fc, fd); rs1[pb][whh][c1] = e;

                // slide +2: drop v1, add v6
                ab = fadd2(ab, v6); ab = ffma2(v1, NG, ab);
                { ull nv = fmul2(v1, NG); cd = ffma2(v6, v6, cd); cd = ffma2(nv, v1, cd); }
                e = fmaf(q3.x, q3.y, e); e = fmaf(-q0.z, q0.w, e);
                upk2(ab, fa, fb); upk2(cd, fc, fd);
                rs4[pb][whh][c2] = make_float4(fa, fb, fc, fd); rs1[pb][whh][c2] = e;

                // slide +3: drop v2, add v7
                ab = fadd2(ab, v7); ab = ffma2(v2, NG, ab);
                { ull nv = fmul2(v2, NG); cd = ffma2(v7, v7, cd); cd = ffma2(nv, v2, cd); }
                e = fmaf(q3.z, q3.w, e); e = fmaf(-q1.x, q1.y, e);
                upk2(ab, fa, fb); upk2(cd, fc, fd);
                rs4[pb][whh][c3] = make_float4(fa, fb, fc, fd); rs1[pb][whh][c3] = e;
            }

            // ---- H-pass on slice s-1 (reads rs[qb], written last iteration) ----
            if (i != 0) {
                const int r0 = 2 * ty;
                float4 q0 = rs4[qb][r0 + 0][swc]; float e0 = rs1[qb][r0 + 0][swc];
                float4 q1 = rs4[qb][r0 + 1][swc]; float e1 = rs1[qb][r0 + 1][swc];
                float4 q2 = rs4[qb][r0 + 2][swc]; float e2 = rs1[qb][r0 + 2][swc];
                float4 q3 = rs4[qb][r0 + 3][swc]; float e3 = rs1[qb][r0 + 3][swc];
                float4 q4 = rs4[qb][r0 + 4][swc]; float e4 = rs1[qb][r0 + 4][swc];
                float4 q5 = rs4[qb][r0 + 5][swc]; float e5 = rs1[qb][r0 + 5][swc];

                ull ab0 = pk2(q0.x, q0.y), cd0 = pk2(q0.z, q0.w);
                ull ab1 = pk2(q1.x, q1.y), cd1 = pk2(q1.z, q1.w);
                ull ab2 = pk2(q2.x, q2.y), cd2 = pk2(q2.z, q2.w);
                ull ab3 = pk2(q3.x, q3.y), cd3 = pk2(q3.z, q3.w);
                ull ab4 = pk2(q4.x, q4.y), cd4 = pk2(q4.z, q4.w);
                ull ab5 = pk2(q5.x, q5.y), cd5 = pk2(q5.z, q5.w);

                ull mAB = fadd2(fadd2(ab1, ab2), fadd2(ab3, ab4));
                ull mCD = fadd2(fadd2(cd1, cd2), fadd2(cd3, cd4));
                float mE = (e1 + e2) + (e3 + e4);

                ull sAB0 = fadd2(mAB, ab0), sAB1 = fadd2(mAB, ab5);
                ull sCD0 = fadd2(mCD, cd0), sCD1 = fadd2(mCD, cd5);
                float sE0 = mE + e0, sE1 = mE + e5;

                // ring: t += s - r[k]; r[k] = s   (slot k = value pushed 5 iters ago)
                tAB[0] = ffma2(rAB[0][k], NG, fadd2(tAB[0], sAB0)); rAB[0][k] = sAB0;
                tCD[0] = ffma2(rCD[0][k], NG, fadd2(tCD[0], sCD0)); rCD[0][k] = sCD0;
                tE[0] += sE0 - rE[0][k]; rE[0][k] = sE0;

                tAB[1] = ffma2(rAB[1][k], NG, fadd2(tAB[1], sAB1)); rAB[1][k] = sAB1;
                tCD[1] = ffma2(rCD[1][k], NG, fadd2(tCD[1], sCD1)); rCD[1][k] = sCD1;
                tE[1] += sE1 - rE[1][k]; rE[1][k] = sE1;

                // ---- emit cc for output slice z = z0 - 5 + i ----
                if (i >= 5) {
                    #pragma unroll
                    for (int r = 0; r < 2; ++r) {
                        float a, b, c, d;
                        upk2(tAB[r], a, b);
                        upk2(tCD[r], c, d);
                        float ai = a * VINV;
                        float bi = b * VINV;
                        float cross = fmaf(-ai, b, tE[r]);
                        float Ivar  = fmaf(-ai, a, c);
                        float Jvar  = fmaf(-bi, b, d);
                        local_cc += __fdividef(cross * cross, fmaf(Ivar, Jvar, EPSV));
                    }
                }
            }
        }
    }

    // ---- block reduction ----
    float v = local_cc;
    #pragma unroll
    for (int off = 16; off > 0; off >>= 1)
        v += __shfl_xor_sync(0xFFFFFFFFu, v, off);
    if (tx == 0) redbuf[ty] = v;
    __syncthreads();
    if (tid < 8) {
        float w = redbuf[tid];
        #pragma unroll
        for (int off = 4; off > 0; off >>= 1)
            w += __shfl_xor_sync(0xFFu, w, off);
        if (tid == 0) atomicAdd(&g_acc, (double)w);
    }
}

extern "C" void kernel_launch(void* const* d_in, const int* in_sizes, int n_in,
                              void* d_out, int out_size) {
    const float* I = (const float*)d_in[0];
    const float* J = (const float*)d_in[1];
    float* out = (float*)d_out;

    dim3 block(NTHREADS);
    dim3 grid(WW / TILE_W, HH / TILE_H, NN * 2);   // 6 x 12 x 4 = 288 blocks, 1 wave @ occ 2
    ncc_main_kernel<<<grid, block>>>(I, J);

    ncc_finalize_kernel<<<1, 1>>>(out);
}

// round 11
// speedup vs baseline: 2.5135x; 1.0228x over previous
#include <cuda_runtime.h>

// Problem constants
#define NN 2
#define DD 160
#define HH 192
#define WW 192
#define HW (HH * WW)

#define TILE_W 32
#define TILE_H 8           // per CTA; 2 output rows per thread
#define HALO_W 36
#define HALO_H 12
#define ROW_BYTES 144      // halo row in a plane: 36 floats (16B-aligned)
#define PLANE_BYTES (HALO_H * ROW_BYTES)      // 1728
#define SLICE_BYTES (2 * PLANE_BYTES)         // 3456 (I plane + J plane)
#define PAIR_BYTES (2 * SLICE_BYTES)          // 6912
#define RING_BYTES (3 * PAIR_BYTES)           // 20736 (triple-buffered pair ring)

#define RROW 33            // padded rs row stride (float4 / float units)
#define RS_ROWS 24         // 2 slices x 12 halo rows
#define RS4_OFF RING_BYTES                      // 20736, 16B aligned
#define RS4_BYTES (2 * RS_ROWS * RROW * 16)     // 25344
#define RS1_OFF (RS4_OFF + RS4_BYTES)           // 46080
#define RS1_BYTES (2 * RS_ROWS * RROW * 4)      // 6336
#define RED_OFF (RS1_OFF + RS1_BYTES)           // 52416
#define DYN_TOTAL (RED_OFF + 16)                // 52432

#define NTHREADS 128
#define CHUNK 80
#define STAGE_ELEMS (HALO_H * HALO_W)         // 432 -> 4 per thread (last guarded)
#define NBLOCKS (6 * 24 * 4)                  // 576 = one wave @ occ 4

#define VINV (1.0f / 125.0f)
#define EPSV 1e-5f
#define NG2 0xBF800000BF800000ULL             // packed (-1.0f, -1.0f)

typedef unsigned long long ull;

// ---- packed f32x2 helpers (sm_103a; ptxas never auto-fuses) ----
__device__ __forceinline__ ull pk2(float lo, float hi) {
    ull r; asm("mov.b64 %0, {%1, %2};" : "=l"(r) : "f"(lo), "f"(hi)); return r;
}
__device__ __forceinline__ void upk2(ull v, float& lo, float& hi) {
    asm("mov.b64 {%0, %1}, %2;" : "=f"(lo), "=f"(hi) : "l"(v));
}
__device__ __forceinline__ ull fadd2(ull a, ull b) {
    ull r; asm("add.rn.f32x2 %0, %1, %2;" : "=l"(r) : "l"(a), "l"(b)); return r;
}
__device__ __forceinline__ ull fmul2(ull a, ull b) {
    ull r; asm("mul.rn.f32x2 %0, %1, %2;" : "=l"(r) : "l"(a), "l"(b)); return r;
}
__device__ __forceinline__ ull ffma2(ull a, ull b, ull c) {
    ull r; asm("fma.rn.f32x2 %0, %1, %2, %3;" : "=l"(r) : "l"(a), "l"(b), "l"(c)); return r;
}

// 4-byte cp.async with runtime src-size (0 -> zero-fill, no gmem read)
__device__ __forceinline__ void cpa4(unsigned dst, const float* src, unsigned sz) {
    asm volatile("cp.async.ca.shared.global [%0], [%1], 4, %2;"
                 :: "r"(dst), "l"(src), "r"(sz) : "memory");
}

__device__ double g_acc;        // static-init 0; last block resets (graph replay safe)
__device__ unsigned g_cnt;      // static-init 0; last block resets

// ---- W-pass: sliding 5-tap W sums over 8 inputs -> 4 outputs, 5 fields ----
__device__ __forceinline__ void w_task(const char* sl, float4* r4, float* r1,
                                       int c0, int c1, int c2, int c3) {
    const float4* pI = reinterpret_cast<const float4*>(sl);
    const float4* pJ = reinterpret_cast<const float4*>(sl + PLANE_BYTES);
    float4 a0 = pI[0], a1 = pI[1];       // I: x0..x7
    float4 b0 = pJ[0], b1 = pJ[1];       // J: y0..y7

    ull v0 = pk2(a0.x, b0.x), v1 = pk2(a0.y, b0.y);
    ull v2 = pk2(a0.z, b0.z), v3 = pk2(a0.w, b0.w);
    ull v4 = pk2(a1.x, b1.x), v5 = pk2(a1.y, b1.y);
    ull v6 = pk2(a1.z, b1.z), v7 = pk2(a1.w, b1.w);

    ull ab = fadd2(fadd2(fadd2(v0, v1), fadd2(v2, v3)), v4);
    ull cd = fmul2(v0, v0);
    cd = ffma2(v1, v1, cd); cd = ffma2(v2, v2, cd);
    cd = ffma2(v3, v3, cd); cd = ffma2(v4, v4, cd);
    float e = a0.x * b0.x;
    e = fmaf(a0.y, b0.y, e); e = fmaf(a0.z, b0.z, e);
    e = fmaf(a0.w, b0.w, e); e = fmaf(a1.x, b1.x, e);

    float fa, fb, fc, fd;
    upk2(ab, fa, fb); upk2(cd, fc, fd);
    r4[c0] = make_float4(fa, fb, fc, fd); r1[c0] = e;

    ab = fadd2(ab, v5); ab = ffma2(v0, NG2, ab);
    { ull nv = fmul2(v0, NG2); cd = ffma2(v5, v5, cd); cd = ffma2(nv, v0, cd); }
    e = fmaf(a1.y, b1.y, e); e = fmaf(-a0.x, b0.x, e);
    upk2(ab, fa, fb); upk2(cd, fc, fd);
    r4[c1] = make_float4(fa, fb, fc, fd); r1[c1] = e;

    ab = fadd2(ab, v6); ab = ffma2(v1, NG2, ab);
    { ull nv = fmul2(v1, NG2); cd = ffma2(v6, v6, cd); cd = ffma2(nv, v1, cd); }
    e = fmaf(a1.z, b1.z, e); e = fmaf(-a0.y, b0.y, e);
    upk2(ab, fa, fb); upk2(cd, fc, fd);
    r4[c2] = make_float4(fa, fb, fc, fd); r1[c2] = e;

    ab = fadd2(ab, v7); ab = ffma2(v2, NG2, ab);
    { ull nv = fmul2(v2, NG2); cd = ffma2(v7, v7, cd); cd = ffma2(nv, v2, cd); }
    e = fmaf(a1.w, b1.w, e); e = fmaf(-a0.z, b0.z, e);
    upk2(ab, fa, fb); upk2(cd, fc, fd);
    r4[c3] = make_float4(fa, fb, fc, fd); r1[c3] = e;
}

// ---- H-pass + D-ring + emit for one slice (2 output rows per thread) ----
__device__ __forceinline__ void h_slice(
    const float4* R4, const float* R1, int row0, int swc, int k,
    ull (&rAB)[2][5], ull (&rCD)[2][5], float (&rE)[2][5],
    ull (&tAB)[2], ull (&tCD)[2], float (&tE)[2],
    bool em, float& lcc)
{
    float4 q0 = R4[(row0 + 0) * RROW + swc]; float e0 = R1[(row0 + 0) * RROW + swc];
    float4 q1 = R4[(row0 + 1) * RROW + swc]; float e1 = R1[(row0 + 1) * RROW + swc];
    float4 q2 = R4[(row0 + 2) * RROW + swc]; float e2 = R1[(row0 + 2) * RROW + swc];
    float4 q3 = R4[(row0 + 3) * RROW + swc]; float e3 = R1[(row0 + 3) * RROW + swc];
    float4 q4 = R4[(row0 + 4) * RROW + swc]; float e4 = R1[(row0 + 4) * RROW + swc];
    float4 q5 = R4[(row0 + 5) * RROW + swc]; float e5 = R1[(row0 + 5) * RROW + swc];

    ull ab0 = pk2(q0.x, q0.y), cd0 = pk2(q0.z, q0.w);
    ull ab1 = pk2(q1.x, q1.y), cd1 = pk2(q1.z, q1.w);
    ull ab2 = pk2(q2.x, q2.y), cd2 = pk2(q2.z, q2.w);
    ull ab3 = pk2(q3.x, q3.y), cd3 = pk2(q3.z, q3.w);
    ull ab4 = pk2(q4.x, q4.y), cd4 = pk2(q4.z, q4.w);
    ull ab5 = pk2(q5.x, q5.y), cd5 = pk2(q5.z, q5.w);

    ull mAB = fadd2(fadd2(ab1, ab2), fadd2(ab3, ab4));
    ull mCD = fadd2(fadd2(cd1, cd2), fadd2(cd3, cd4));
    float mE = (e1 + e2) + (e3 + e4);

    ull sAB0 = fadd2(mAB, ab0), sAB1 = fadd2(mAB, ab5);
    ull sCD0 = fadd2(mCD, cd0), sCD1 = fadd2(mCD, cd5);
    float sE0 = mE + e0, sE1 = mE + e5;

    tAB[0] = ffma2(rAB[0][k], NG2, fadd2(tAB[0], sAB0)); rAB[0][k] = sAB0;
    tCD[0] = ffma2(rCD[0][k], NG2, fadd2(tCD[0], sCD0)); rCD[0][k] = sCD0;
    tE[0] += sE0 - rE[0][k]; rE[0][k] = sE0;

    tAB[1] = ffma2(rAB[1][k], NG2, fadd2(tAB[1], sAB1)); rAB[1][k] = sAB1;
    tCD[1] = ffma2(rCD[1][k], NG2, fadd2(tCD[1], sCD1)); rCD[1][k] = sCD1;
    tE[1] += sE1 - rE[1][k]; rE[1][k] = sE1;

    if (em) {
        #pragma unroll
        for (int r = 0; r < 2; ++r) {
            float a, b, c, d;
            upk2(tAB[r], a, b);
            upk2(tCD[r], c, d);
            float ai = a * VINV;
            float bi = b * VINV;
            float cross = fmaf(-ai, b, tE[r]);
            float Ivar  = fmaf(-ai, a, c);
            float Jvar  = fmaf(-bi, b, d);
            lcc += __fdividef(cross * cross, fmaf(Ivar, Jvar, EPSV));
        }
    }
}

__global__ __launch_bounds__(NTHREADS, 4)
void ncc_main_kernel(const float* __restrict__ I, const float* __restrict__ J,
                     float* __restrict__ out) {
    extern __shared__ __align__(16) char dynsm[];   // [pair ring | rs4 | rs1 | redbuf]
    float4* RS4 = reinterpret_cast<float4*>(dynsm + RS4_OFF);  // [2][24][RROW]
    float*  RS1 = reinterpret_cast<float*>(dynsm + RS1_OFF);   // [2][24][RROW]
    float*  redbuf = reinterpret_cast<float*>(dynsm + RED_OFF);

    const int tid = threadIdx.x;
    const int tx = tid & 31;
    const int ty = tid >> 5;                 // 0..3 -> output rows 2ty, 2ty+1
    const int w0b = blockIdx.x * TILE_W;
    const int h0b = blockIdx.y * TILE_H;
    const int n   = blockIdx.z >> 1;
    const int z0  = (blockIdx.z & 1) * CHUNK;

    const float* __restrict__ Ibase = I + (size_t)n * DD * HW;
    const float* __restrict__ Jbase = J + (size_t)n * DD * HW;

    unsigned dynu32;
    asm("{ .reg .u64 t; cvta.to.shared.u64 t, %1; cvt.u32.u64 %0, t; }"
        : "=r"(dynu32) : "l"(dynsm));

    // ---- staging mapping: 4 elements per thread (432 total; 4th guarded) ----
    int goff[4];
    unsigned sIo[4];
    #pragma unroll
    for (int t = 0; t < 4; ++t) {
        int e = tid + t * NTHREADS;
        int hh = e / HALO_W, ww = e - hh * HALO_W;
        int gh = h0b - 2 + hh, gw = w0b - 2 + ww;
        bool inb = (e < STAGE_ELEMS) && (gh >= 0 && gh < HH && gw >= 0 && gw < WW);
        goff[t] = inb ? (gh * WW + gw) : -1;
        sIo[t] = (unsigned)(hh * ROW_BYTES + ww * 4);
    }
    const bool has4 = (tid < STAGE_ELEMS - 3 * NTHREADS);   // tid < 48

    // ---- W-pass task mapping: pair = 192 tasks; task1 = tid, task2 = 128+tid (tid<64)
    int s1 = (tid >= 96) ? 1 : 0;
    int r1i = tid - 96 * s1;
    int whh1 = r1i >> 3, wwg1 = r1i & 7;
    const int oIJ1 = s1 * SLICE_BYTES + whh1 * ROW_BYTES + wwg1 * 16;
    const int rsrow1 = s1 * HALO_H + whh1;
    const int c10 = wwg1, c11 = 8 + (wwg1 ^ 2), c12 = 16 + (wwg1 ^ 4), c13 = 24 + (wwg1 ^ 6);

    int r2i = tid + 32;                       // slice 1, tasks 32..95 (tid<64)
    int whh2 = r2i >> 3, wwg2 = r2i & 7;
    const int oIJ2 = SLICE_BYTES + whh2 * ROW_BYTES + wwg2 * 16;
    const int rsrow2 = HALO_H + whh2;
    const int c20 = wwg2, c21 = 8 + (wwg2 ^ 2), c22 = 16 + (wwg2 ^ 4), c23 = 24 + (wwg2 ^ 6);

    // ---- H-pass read column (inverse of store swizzle, logical w = tx) ----
    const int swc = 8 * (tx & 3) + ((tx >> 2) ^ (2 * (tx & 3)));

    // ---- pipeline state ----
    ull rAB[2][5] = {{0,0,0,0,0},{0,0,0,0,0}};
    ull rCD[2][5] = {{0,0,0,0,0},{0,0,0,0,0}};
    float rE[2][5] = {{0,0,0,0,0},{0,0,0,0,0}};
    ull tAB[2] = {0, 0}, tCD[2] = {0, 0};
    float tE[2] = {0.f, 0.f};
    float local_cc = 0.f;

    // ---- async stage of one pair (slices m0, m0+1) into ring buffer at dstoff ----
    auto issue_pair = [&](int m0, unsigned dstoff) {
        #pragma unroll
        for (int s = 0; s < 2; ++s) {
            int z = z0 - 2 + m0 + s;
            bool zv = ((unsigned)z < (unsigned)DD);
            int zc = zv ? z : 0;
            const float* pi = Ibase + (size_t)zc * HW;
            const float* pj = Jbase + (size_t)zc * HW;
            unsigned db = dynu32 + dstoff + (unsigned)(s * SLICE_BYTES);
            #pragma unroll
            for (int t = 0; t < 4; ++t) {
                if (t < 3 || has4) {
                    int go = goff[t];
                    unsigned sz = (zv && go >= 0) ? 4u : 0u;
                    int g2 = (go >= 0) ? go : 0;
                    cpa4(db + sIo[t], pi + g2, sz);
                    cpa4(db + PLANE_BYTES + sIo[t], pj + g2, sz);
                }
            }
        }
        asm volatile("cp.async.commit_group;" ::: "memory");
    };

    // prologue: pair1 (slices 0,1) -> buf0, pair2 (slices 2,3) -> buf1
    issue_pair(0, 0u);
    issue_pair(2, (unsigned)PAIR_BYTES);
    unsigned offW = 0u, offN = PAIR_BYTES, offI = 2u * PAIR_BYTES;

    constexpr int K1[5] = {3, 0, 2, 4, 1};   // (2j+3)%5
    constexpr int K2[5] = {4, 1, 3, 0, 2};   // (2j+4)%5

    for (int g = 0; g < 9; ++g) {
        #pragma unroll
        for (int j = 0; j < 5; ++j) {
            const int p = 1 + 5 * g + j;
            const int pb = p & 1, wb = pb ^ 1;

            asm volatile("cp.async.wait_group 1;" ::: "memory");
            __syncthreads();     // pair p staged in offW; rs[pb] final; rs[wb] free

            // issue stage of pair p+2 (slices 2p+2, 2p+3) into free buffer
            issue_pair(2 * p + 2, offI);

            // ---- W-pass on pair p (slices 2p-2, 2p-1) -> rs[wb] ----
            if (p <= 42) {
                const char* base = dynsm + offW;
                w_task(base + oIJ1,
                       RS4 + (wb * RS_ROWS + rsrow1) * RROW,
                       RS1 + (wb * RS_ROWS + rsrow1) * RROW,
                       c10, c11, c12, c13);
                if (tid < 64)
                    w_task(base + oIJ2,
                           RS4 + (wb * RS_ROWS + rsrow2) * RROW,
                           RS1 + (wb * RS_ROWS + rsrow2) * RROW,
                           c20, c21, c22, c23);
            }

            // ---- H-pass on pair p-1 (slices m=2p-4, 2p-3) from rs[pb] ----
            if (p >= 2 && p <= 43) {
                const bool em = (p >= 4);
                const float4* R4b = RS4 + pb * RS_ROWS * RROW;
                const float*  R1b = RS1 + pb * RS_ROWS * RROW;
                h_slice(R4b, R1b, 2 * ty, swc, K1[j],
                        rAB, rCD, rE, tAB, tCD, tE, em, local_cc);
                h_slice(R4b + HALO_H * RROW, R1b + HALO_H * RROW, 2 * ty, swc, K2[j],
                        rAB, rCD, rE, tAB, tCD, tE, em, local_cc);
            }

            unsigned t0 = offW; offW = offN; offN = offI; offI = t0;
        }
    }

    asm volatile("cp.async.wait_group 0;" ::: "memory");

    // ---- block reduction + fused finalize (last block writes out) ----
    float v = local_cc;
    #pragma unroll
    for (int off = 16; off > 0; off >>= 1)
        v += __shfl_xor_sync(0xFFFFFFFFu, v, off);
    __syncthreads();               // rs/red space free
    if (tx == 0) redbuf[ty] = v;
    __syncthreads();
    if (tid == 0) {
        float w = (redbuf[0] + redbuf[1]) + (redbuf[2] + redbuf[3]);
        atomicAdd(&g_acc, (double)w);
        __threadfence();
        unsigned t = atomicAdd(&g_cnt, 1u);
        if (t == NBLOCKS - 1) {
            double total = *((volatile double*)&g_acc);
            out[0] = (float)(-total / ((double)NN * DD * HH * WW));
            g_acc = 0.0;          // reset for next graph replay
            g_cnt = 0u;
        }
    }
}

extern "C" void kernel_launch(void* const* d_in, const int* in_sizes, int n_in,
                              void* d_out, int out_size) {
    const float* I = (const float*)d_in[0];
    const float* J = (const float*)d_in[1];
    float* out = (float*)d_out;

    // Opt in to >48KB combined shared memory (idempotent; non-stream host call,
    // legal during graph capture).
    cudaFuncSetAttribute(ncc_main_kernel,
                         cudaFuncAttributeMaxDynamicSharedMemorySize, DYN_TOTAL);

    dim3 block(NTHREADS);
    dim3 grid(WW / TILE_W, HH / TILE_H, NN * 2);   // 6 x 24 x 4 = 576 blocks
    ncc_main_kernel<<<grid, block, DYN_TOTAL>>>(I, J, out);
}

// round 15
// speedup vs baseline: 2.8008x; 1.1143x over previous
#include <cuda_runtime.h>

// Problem constants
#define NN 2
#define DD 160
#define HH 192
#define WW 192
#define HW (HH * WW)

#define TILE_W 32
#define TILE_H 16          // per CTA; 2 output rows per thread (8 ty-groups)
#define HALO_W 36
#define HALO_H 20
#define ROW_BYTES 144      // halo row in a plane: 36 floats (16B-aligned)
#define PLANE_BYTES (HALO_H * ROW_BYTES)      // 2880
#define SLICE_BYTES (2 * PLANE_BYTES)         // 5760 (I plane + J plane)
#define PAIR_BYTES (2 * SLICE_BYTES)          // 11520
#define RING_BYTES (3 * PAIR_BYTES)           // 34560 (triple-buffered pair ring)

#define RROW 33            // padded rs row stride (float4 / float units)
#define RS_ROWS 40         // 2 slices x 20 halo rows
#define RS4_OFF RING_BYTES                      // 34560, 16B aligned
#define RS4_BYTES (2 * RS_ROWS * RROW * 16)     // 42240
#define RS1_OFF (RS4_OFF + RS4_BYTES)           // 76800
#define RS1_BYTES (2 * RS_ROWS * RROW * 4)      // 10560
#define RED_OFF (RS1_OFF + RS1_BYTES)           // 87360
#define DYN_TOTAL (RED_OFF + 32)                // 87392

#define NTHREADS 256
#define CHUNK 80
#define CHUNKS_PER_SLICE 18                   // 36 floats / 2 per 8B chunk
#define SL_CHUNKS (HALO_H * CHUNKS_PER_SLICE) // 360 per plane
#define SL_CHUNKS2 (2 * SL_CHUNKS)            // 720 per slice (I+J)
#define NBLOCKS (6 * 12 * 4)                  // 288 = one wave @ occ 2

#define VINV (1.0f / 125.0f)
#define EPSV 1e-5f
#define NG2 0xBF800000BF800000ULL             // packed (-1.0f, -1.0f)

typedef unsigned long long ull;

// ---- packed f32x2 helpers (sm_103a; ptxas never auto-fuses) ----
__device__ __forceinline__ ull pk2(float lo, float hi) {
    ull r; asm("mov.b64 %0, {%1, %2};" : "=l"(r) : "f"(lo), "f"(hi)); return r;
}
__device__ __forceinline__ void upk2(ull v, float& lo, float& hi) {
    asm("mov.b64 {%0, %1}, %2;" : "=f"(lo), "=f"(hi) : "l"(v));
}
__device__ __forceinline__ ull fadd2(ull a, ull b) {
    ull r; asm("add.rn.f32x2 %0, %1, %2;" : "=l"(r) : "l"(a), "l"(b)); return r;
}
__device__ __forceinline__ ull fmul2(ull a, ull b) {
    ull r; asm("mul.rn.f32x2 %0, %1, %2;" : "=l"(r) : "l"(a), "l"(b)); return r;
}
__device__ __forceinline__ ull ffma2(ull a, ull b, ull c) {
    ull r; asm("fma.rn.f32x2 %0, %1, %2, %3;" : "=l"(r) : "l"(a), "l"(b), "l"(c)); return r;
}

// 8-byte cp.async with runtime src-size (0 -> zero-fill, no gmem read)
__device__ __forceinline__ void cpa8(unsigned dst, const float* src, unsigned sz) {
    asm volatile("cp.async.ca.shared.global [%0], [%1], 8, %2;"
                 :: "r"(dst), "l"(src), "r"(sz) : "memory");
}

__device__ double g_acc;        // static-init 0; last block resets (graph replay safe)
__device__ unsigned g_cnt;      // static-init 0; last block resets

// ---- W-pass: sliding 5-tap W sums over 8 inputs -> 4 outputs, 5 fields ----
__device__ __forceinline__ void w_task(const char* sl, float4* r4, float* r1,
                                       int c0, int c1, int c2, int c3) {
    const float4* pI = reinterpret_cast<const float4*>(sl);
    const float4* pJ = reinterpret_cast<const float4*>(sl + PLANE_BYTES);
    float4 a0 = pI[0], a1 = pI[1];       // I: x0..x7
    float4 b0 = pJ[0], b1 = pJ[1];       // J: y0..y7

    ull v0 = pk2(a0.x, b0.x), v1 = pk2(a0.y, b0.y);
    ull v2 = pk2(a0.z, b0.z), v3 = pk2(a0.w, b0.w);
    ull v4 = pk2(a1.x, b1.x), v5 = pk2(a1.y, b1.y);
    ull v6 = pk2(a1.z, b1.z), v7 = pk2(a1.w, b1.w);

    ull ab = fadd2(fadd2(fadd2(v0, v1), fadd2(v2, v3)), v4);
    ull cd = fmul2(v0, v0);
    cd = ffma2(v1, v1, cd); cd = ffma2(v2, v2, cd);
    cd = ffma2(v3, v3, cd); cd = ffma2(v4, v4, cd);
    float e = a0.x * b0.x;
    e = fmaf(a0.y, b0.y, e); e = fmaf(a0.z, b0.z, e);
    e = fmaf(a0.w, b0.w, e); e = fmaf(a1.x, b1.x, e);

    float fa, fb, fc, fd;
    upk2(ab, fa, fb); upk2(cd, fc, fd);
    r4[c0] = make_float4(fa, fb, fc, fd); r1[c0] = e;

    ab = fadd2(ab, v5); ab = ffma2(v0, NG2, ab);
    { ull nv = fmul2(v0, NG2); cd = ffma2(v5, v5, cd); cd = ffma2(nv, v0, cd); }
    e = fmaf(a1.y, b1.y, e); e = fmaf(-a0.x, b0.x, e);
    upk2(ab, fa, fb); upk2(cd, fc, fd);
    r4[c1] = make_float4(fa, fb, fc, fd); r1[c1] = e;

    ab = fadd2(ab, v6); ab = ffma2(v1, NG2, ab);
    { ull nv = fmul2(v1, NG2); cd = ffma2(v6, v6, cd); cd = ffma2(nv, v1, cd); }
    e = fmaf(a1.z, b1.z, e); e = fmaf(-a0.y, b0.y, e);
    upk2(ab, fa, fb); upk2(cd, fc, fd);
    r4[c2] = make_float4(fa, fb, fc, fd); r1[c2] = e;

    ab = fadd2(ab, v7); ab = ffma2(v2, NG2, ab);
    { ull nv = fmul2(v2, NG2); cd = ffma2(v7, v7, cd); cd = ffma2(nv, v2, cd); }
    e = fmaf(a1.w, b1.w, e); e = fmaf(-a0.z, b0.z, e);
    upk2(ab, fa, fb); upk2(cd, fc, fd);
    r4[c3] = make_float4(fa, fb, fc, fd); r1[c3] = e;
}

// ---- H-pass + D-ring + emit for one slice (2 output rows per thread) ----
__device__ __forceinline__ void h_slice(
    const float4* R4, const float* R1, int row0, int swc, int k,
    ull (&rAB)[2][5], ull (&rCD)[2][5], float (&rE)[2][5],
    ull (&tAB)[2], ull (&tCD)[2], float (&tE)[2],
    bool em, float& lcc)
{
    float4 q0 = R4[(row0 + 0) * RROW + swc]; float e0 = R1[(row0 + 0) * RROW + swc];
    float4 q1 = R4[(row0 + 1) * RROW + swc]; float e1 = R1[(row0 + 1) * RROW + swc];
    float4 q2 = R4[(row0 + 2) * RROW + swc]; float e2 = R1[(row0 + 2) * RROW + swc];
    float4 q3 = R4[(row0 + 3) * RROW + swc]; float e3 = R1[(row0 + 3) * RROW + swc];
    float4 q4 = R4[(row0 + 4) * RROW + swc]; float e4 = R1[(row0 + 4) * RROW + swc];
    float4 q5 = R4[(row0 + 5) * RROW + swc]; float e5 = R1[(row0 + 5) * RROW + swc];

    ull ab0 = pk2(q0.x, q0.y), cd0 = pk2(q0.z, q0.w);
    ull ab1 = pk2(q1.x, q1.y), cd1 = pk2(q1.z, q1.w);
    ull ab2 = pk2(q2.x, q2.y), cd2 = pk2(q2.z, q2.w);
    ull ab3 = pk2(q3.x, q3.y), cd3 = pk2(q3.z, q3.w);
    ull ab4 = pk2(q4.x, q4.y), cd4 = pk2(q4.z, q4.w);
    ull ab5 = pk2(q5.x, q5.y), cd5 = pk2(q5.z, q5.w);

    ull mAB = fadd2(fadd2(ab1, ab2), fadd2(ab3, ab4));
    ull mCD = fadd2(fadd2(cd1, cd2), fadd2(cd3, cd4));
    float mE = (e1 + e2) + (e3 + e4);

    ull sAB0 = fadd2(mAB, ab0), sAB1 = fadd2(mAB, ab5);
    ull sCD0 = fadd2(mCD, cd0), sCD1 = fadd2(mCD, cd5);
    float sE0 = mE + e0, sE1 = mE + e5;

    tAB[0] = ffma2(rAB[0][k], NG2, fadd2(tAB[0], sAB0)); rAB[0][k] = sAB0;
    tCD[0] = ffma2(rCD[0][k], NG2, fadd2(tCD[0], sCD0)); rCD[0][k] = sCD0;
    tE[0] += sE0 - rE[0][k]; rE[0][k] = sE0;

    tAB[1] = ffma2(rAB[1][k], NG2, fadd2(tAB[1], sAB1)); rAB[1][k] = sAB1;
    tCD[1] = ffma2(rCD[1][k], NG2, fadd2(tCD[1], sCD1)); rCD[1][k] = sCD1;
    tE[1] += sE1 - rE[1][k]; rE[1][k] = sE1;

    if (em) {
        #pragma unroll
        for (int r = 0; r < 2; ++r) {
            float a, b, c, d;
            upk2(tAB[r], a, b);
            upk2(tCD[r], c, d);
            float ai = a * VINV;
            float bi = b * VINV;
            float cross = fmaf(-ai, b, tE[r]);
            float Ivar  = fmaf(-ai, a, c);
            float Jvar  = fmaf(-bi, b, d);
            lcc += __fdividef(cross * cross, fmaf(Ivar, Jvar, EPSV));
        }
    }
}

__global__ __launch_bounds__(NTHREADS, 2)
void ncc_main_kernel(const float* __restrict__ I, const float* __restrict__ J,
                     float* __restrict__ out) {
    extern __shared__ __align__(16) char dynsm[];   // [pair ring | rs4 | rs1 | redbuf]
    float4* RS4 = reinterpret_cast<float4*>(dynsm + RS4_OFF);  // [2][40][RROW]
    float*  RS1 = reinterpret_cast<float*>(dynsm + RS1_OFF);   // [2][40][RROW]
    float*  redbuf = reinterpret_cast<float*>(dynsm + RED_OFF);

    const int tid = threadIdx.x;
    const int tx = tid & 31;
    const int ty = tid >> 5;                 // 0..7 -> output rows 2ty, 2ty+1
    const int w0b = blockIdx.x * TILE_W;
    const int h0b = blockIdx.y * TILE_H;
    const int n   = blockIdx.z >> 1;
    const int z0  = (blockIdx.z & 1) * CHUNK;

    const float* __restrict__ Ibase = I + (size_t)n * DD * HW;
    const float* __restrict__ Jbase = J + (size_t)n * DD * HW;

    unsigned dynu32;
    asm("{ .reg .u64 t; cvta.to.shared.u64 t, %1; cvt.u32.u64 %0, t; }"
        : "=r"(dynu32) : "l"(dynsm));

    // ---- staging mapping: 8B chunks; 720 per slice, 3 per thread (3rd guarded) ----
    // chunk id e: plane = e/360, r = e%360, hh = r/18, cc = r%18
    // gmem: row gh = h0b-2+hh, cols gw = w0b-2+2cc (all-in or all-out of bounds)
    int  goff[3];      // element offset within a slice, or -1 (zero-fill)
    unsigned soff[3];  // smem byte offset within a slice buffer (incl. plane)
    bool pfl[3];       // false=I plane, true=J plane
    #pragma unroll
    for (int t = 0; t < 3; ++t) {
        int e = tid + t * NTHREADS;
        int pl = (e >= SL_CHUNKS) ? 1 : 0;
        int r = e - pl * SL_CHUNKS;
        int hh = r / CHUNKS_PER_SLICE, cc = r - hh * CHUNKS_PER_SLICE;
        int gh = h0b - 2 + hh;
        int gw = w0b - 2 + 2 * cc;
        bool inb = (e < SL_CHUNKS2) && (gh >= 0 && gh < HH) && (gw >= 0 && gw < WW - 1);
        goff[t] = inb ? (gh * WW + gw) : -1;
        soff[t] = (unsigned)(pl * PLANE_BYTES + hh * ROW_BYTES + 8 * cc);
        pfl[t] = (pl != 0);
    }
    const bool has3 = (tid < SL_CHUNKS2 - 2 * NTHREADS);   // tid < 208

    // ---- W-pass task mapping: 320 tasks/pair; t1 = tid, t2 = 256+tid (tid<64) ----
    int s1 = (tid >= 160) ? 1 : 0;
    int r1i = tid - 160 * s1;
    int whh1 = r1i >> 3, wwg1 = r1i & 7;
    const int oIJ1 = s1 * SLICE_BYTES + whh1 * ROW_BYTES + wwg1 * 16;
    const int rsrow1 = s1 * HALO_H + whh1;
    const int c10 = wwg1, c11 = 8 + (wwg1 ^ 2), c12 = 16 + (wwg1 ^ 4), c13 = 24 + (wwg1 ^ 6);

    int r2i = tid + 96;                       // slice 1, rows 12..19 (tid<64)
    int whh2 = r2i >> 3, wwg2 = r2i & 7;
    const int oIJ2 = SLICE_BYTES + whh2 * ROW_BYTES + wwg2 * 16;
    const int rsrow2 = HALO_H + whh2;
    const int c20 = wwg2, c21 = 8 + (wwg2 ^ 2), c22 = 16 + (wwg2 ^ 4), c23 = 24 + (wwg2 ^ 6);

    // ---- H-pass read column (inverse of store swizzle, logical w = tx) ----
    const int swc = 8 * (tx & 3) + ((tx >> 2) ^ (2 * (tx & 3)));

    // ---- pipeline state ----
    ull rAB[2][5] = {{0,0,0,0,0},{0,0,0,0,0}};
    ull rCD[2][5] = {{0,0,0,0,0},{0,0,0,0,0}};
    float rE[2][5] = {{0,0,0,0,0},{0,0,0,0,0}};
    ull tAB[2] = {0, 0}, tCD[2] = {0, 0};
    float tE[2] = {0.f, 0.f};
    float local_cc = 0.f;

    // ---- async stage of one pair (slices m0, m0+1) into ring buffer at dstoff ----
    auto issue_pair = [&](int m0, unsigned dstoff) {
        #pragma unroll
        for (int s = 0; s < 2; ++s) {
            int z = z0 - 2 + m0 + s;
            bool zv = ((unsigned)z < (unsigned)DD);
            int zc = zv ? z : 0;
            const float* pi = Ibase + (size_t)zc * HW;
            const float* pj = Jbase + (size_t)zc * HW;
            unsigned db = dynu32 + dstoff + (unsigned)(s * SLICE_BYTES);
            #pragma unroll
            for (int t = 0; t < 3; ++t) {
                if (t < 2 || has3) {
                    int go = goff[t];
                    unsigned sz = (zv && go >= 0) ? 8u : 0u;
                    int g2 = (go >= 0) ? go : 0;
                    const float* src = (pfl[t] ? pj : pi) + g2;
                    cpa8(db + soff[t], src, sz);
                }
            }
        }
        asm volatile("cp.async.commit_group;" ::: "memory");
    };

    // prologue: pair1 (slices 0,1) -> buf0, pair2 (slices 2,3) -> buf1
    issue_pair(0, 0u);
    issue_pair(2, (unsigned)PAIR_BYTES);
    unsigned offW = 0u, offN = PAIR_BYTES, offI = 2u * PAIR_BYTES;

    constexpr int K1[5] = {3, 0, 2, 4, 1};   // (2j+3)%5
    constexpr int K2[5] = {4, 1, 3, 0, 2};   // (2j+4)%5

    for (int g = 0; g < 9; ++g) {
        #pragma unroll
        for (int j = 0; j < 5; ++j) {
            const int p = 1 + 5 * g + j;
            const int pb = p & 1, wb = pb ^ 1;

            asm volatile("cp.async.wait_group 1;" ::: "memory");
            __syncthreads();     // pair p staged in offW; rs[pb] final; rs[wb] free

            // issue stage of pair p+2 (slices 2p+2, 2p+3) into free buffer
            issue_pair(2 * p + 2, offI);

            // ---- W-pass on pair p (slices 2p-2, 2p-1) -> rs[wb] ----
            if (p <= 42) {
                const char* base = dynsm + offW;
                w_task(base + oIJ1,
                       RS4 + (wb * RS_ROWS + rsrow1) * RROW,
                       RS1 + (wb * RS_ROWS + rsrow1) * RROW,
                       c10, c11, c12, c13);
                if (tid < 64)
                    w_task(base + oIJ2,
                           RS4 + (wb * RS_ROWS + rsrow2) * RROW,
                           RS1 + (wb * RS_ROWS + rsrow2) * RROW,
                           c20, c21, c22, c23);
            }

            // ---- H-pass on pair p-1 (slices m=2p-4, 2p-3) from rs[pb] ----
            if (p >= 2 && p <= 43) {
                const bool em = (p >= 4);
                const float4* R4b = RS4 + pb * RS_ROWS * RROW;
                const float*  R1b = RS1 + pb * RS_ROWS * RROW;
                h_slice(R4b, R1b, 2 * ty, swc, K1[j],
                        rAB, rCD, rE, tAB, tCD, tE, em, local_cc);
                h_slice(R4b + HALO_H * RROW, R1b + HALO_H * RROW, 2 * ty, swc, K2[j],
                        rAB, rCD, rE, tAB, tCD, tE, em, local_cc);
            }

            unsigned t0 = offW; offW = offN; offN = offI; offI = t0;
        }
    }

    asm volatile("cp.async.wait_group 0;" ::: "memory");

    // ---- block reduction + fused finalize (last block writes out) ----
    float v = local_cc;
    #pragma unroll
    for (int off = 16; off > 0; off >>= 1)
        v += __shfl_xor_sync(0xFFFFFFFFu, v, off);
    __syncthreads();               // rs/red space free
    if (tx == 0) redbuf[ty] = v;
    __syncthreads();
    if (tid == 0) {
        float w = ((redbuf[0] + redbuf[1]) + (redbuf[2] + redbuf[3]))
                + ((redbuf[4] + redbuf[5]) + (redbuf[6] + redbuf[7]));
        atomicAdd(&g_acc, (double)w);
        __threadfence();
        unsigned t = atomicAdd(&g_cnt, 1u);
        if (t == NBLOCKS - 1) {
            double total = *((volatile double*)&g_acc);
            out[0] = (float)(-total / ((double)NN * DD * HH * WW));
            g_acc = 0.0;          // reset for next graph replay
            g_cnt = 0u;
        }
    }
}

extern "C" void kernel_launch(void* const* d_in, const int* in_sizes, int n_in,
                              void* d_out, int out_size) {
    const float* I = (const float*)d_in[0];
    const float* J = (const float*)d_in[1];
    float* out = (float*)d_out;

    // Opt in to >48KB combined shared memory (idempotent; non-stream host call,
    // legal during graph capture).
    cudaFuncSetAttribute(ncc_main_kernel,
                         cudaFuncAttributeMaxDynamicSharedMemorySize, DYN_TOTAL);

    dim3 block(NTHREADS);
    dim3 grid(WW / TILE_W, HH / TILE_H, NN * 2);   // 6 x 12 x 4 = 288 blocks
    ncc_main_kernel<<<grid, block, DYN_TOTAL>>>(I, J, out);
}

// round 16
// speedup vs baseline: 3.1483x; 1.1241x over previous
#include <cuda_runtime.h>

// Problem constants
#define NN 2
#define DD 160
#define HH 192
#define WW 192
#define HW (HH * WW)

#define TILE_W 32
#define TILE_H 16          // per CTA; 2 output rows per thread (8 ty-groups)
#define HALO_W 36
#define HALO_H 20
#define ROW_BYTES 144      // halo row in a plane: 36 floats (16B-aligned)
#define PLANE_BYTES (HALO_H * ROW_BYTES)      // 2880
#define SLICE_BYTES (2 * PLANE_BYTES)         // 5760 (I plane + J plane)
#define PAIR_BYTES (2 * SLICE_BYTES)          // 11520
#define RING_BYTES (3 * PAIR_BYTES)           // 34560 (triple-buffered pair ring)

#define RROW  33           // E (f32) row stride
#define RROWH 40           // ABCD (uint2 = 2x half2) row stride; 40 mod 16 == 8 -> conflict-free
#define RS_ROWS 40         // 2 slices x 20 halo rows
#define RS4H_OFF RING_BYTES                     // 34560 (8B aligned)
#define RS4H_BYTES (2 * RS_ROWS * RROWH * 8)    // 25600
#define RS1_OFF (RS4H_OFF + RS4H_BYTES)         // 60160
#define RS1_BYTES (2 * RS_ROWS * RROW * 4)      // 10560
#define RED_OFF (RS1_OFF + RS1_BYTES)           // 70720
#define DYN_TOTAL (RED_OFF + 32)                // 70752

#define NTHREADS 256
#define CHUNK 80
#define CHUNKS_PER_SLICE 18                   // 36 floats / 2 per 8B chunk
#define SL_CHUNKS (HALO_H * CHUNKS_PER_SLICE) // 360 per plane
#define SL_CHUNKS2 (2 * SL_CHUNKS)            // 720 per slice (I+J)
#define NBLOCKS (6 * 12 * 4)                  // 288 = one wave @ occ 2

#define VINV (1.0f / 125.0f)
#define EPSV 1e-5f
#define NG2 0xBF800000BF800000ULL             // packed (-1.0f, -1.0f)

typedef unsigned long long ull;

// ---- packed f32x2 helpers (sm_103a; ptxas never auto-fuses) ----
__device__ __forceinline__ ull pk2(float lo, float hi) {
    ull r; asm("mov.b64 %0, {%1, %2};" : "=l"(r) : "f"(lo), "f"(hi)); return r;
}
__device__ __forceinline__ void upk2(ull v, float& lo, float& hi) {
    asm("mov.b64 {%0, %1}, %2;" : "=f"(lo), "=f"(hi) : "l"(v));
}
__device__ __forceinline__ ull fadd2(ull a, ull b) {
    ull r; asm("add.rn.f32x2 %0, %1, %2;" : "=l"(r) : "l"(a), "l"(b)); return r;
}
__device__ __forceinline__ ull fmul2(ull a, ull b) {
    ull r; asm("mul.rn.f32x2 %0, %1, %2;" : "=l"(r) : "l"(a), "l"(b)); return r;
}
__device__ __forceinline__ ull ffma2(ull a, ull b, ull c) {
    ull r; asm("fma.rn.f32x2 %0, %1, %2, %3;" : "=l"(r) : "l"(a), "l"(b), "l"(c)); return r;
}

// ---- fp16 pack/convert helpers ----
// pack two f32 -> half2 (h0 = lo, h1 = hi); first cvt operand fills the UPPER half
__device__ __forceinline__ unsigned pkh2(float lo, float hi) {
    unsigned r;
    asm("cvt.rn.f16x2.f32 %0, %1, %2;" : "=r"(r) : "f"(hi), "f"(lo));
    return r;
}
__device__ __forceinline__ unsigned hadd2u(unsigned a, unsigned b) {
    unsigned r; asm("add.rn.f16x2 %0, %1, %2;" : "=r"(r) : "r"(a), "r"(b)); return r;
}
// half2 -> packed f32x2 (lo = h0, hi = h1)
__device__ __forceinline__ ull h2f2(unsigned h) {
    ull r;
    asm("{\n\t"
        ".reg .b16 lo16, hi16;\n\t"
        ".reg .f32 flo, fhi;\n\t"
        "mov.b32 {lo16, hi16}, %1;\n\t"
        "cvt.f32.f16 flo, lo16;\n\t"
        "cvt.f32.f16 fhi, hi16;\n\t"
        "mov.b64 %0, {flo, fhi};\n\t"
        "}" : "=l"(r) : "r"(h));
    return r;
}

// 8-byte cp.async with runtime src-size (0 -> zero-fill, no gmem read)
__device__ __forceinline__ void cpa8(unsigned dst, const float* src, unsigned sz) {
    asm volatile("cp.async.ca.shared.global [%0], [%1], 8, %2;"
                 :: "r"(dst), "l"(src), "r"(sz) : "memory");
}

__device__ double g_acc;        // static-init 0; last block resets (graph replay safe)
__device__ unsigned g_cnt;      // static-init 0; last block resets

// ---- W-pass: sliding 5-tap W sums over 8 inputs -> 4 outputs, 5 fields ----
// ABCD computed in f32x2, stored as {half2(A,B), half2(C,D)}; E stays f32.
__device__ __forceinline__ void w_task(const char* sl, uint2* r4h, float* r1,
                                       int c0, int c1, int c2, int c3) {
    const float4* pI = reinterpret_cast<const float4*>(sl);
    const float4* pJ = reinterpret_cast<const float4*>(sl + PLANE_BYTES);
    float4 a0 = pI[0], a1 = pI[1];       // I: x0..x7
    float4 b0 = pJ[0], b1 = pJ[1];       // J: y0..y7

    ull v0 = pk2(a0.x, b0.x), v1 = pk2(a0.y, b0.y);
    ull v2 = pk2(a0.z, b0.z), v3 = pk2(a0.w, b0.w);
    ull v4 = pk2(a1.x, b1.x), v5 = pk2(a1.y, b1.y);
    ull v6 = pk2(a1.z, b1.z), v7 = pk2(a1.w, b1.w);

    ull ab = fadd2(fadd2(fadd2(v0, v1), fadd2(v2, v3)), v4);
    ull cd = fmul2(v0, v0);
    cd = ffma2(v1, v1, cd); cd = ffma2(v2, v2, cd);
    cd = ffma2(v3, v3, cd); cd = ffma2(v4, v4, cd);
    float e = a0.x * b0.x;
    e = fmaf(a0.y, b0.y, e); e = fmaf(a0.z, b0.z, e);
    e = fmaf(a0.w, b0.w, e); e = fmaf(a1.x, b1.x, e);

    float fa, fb, fc, fd;
    upk2(ab, fa, fb); upk2(cd, fc, fd);
    r4h[c0] = make_uint2(pkh2(fa, fb), pkh2(fc, fd)); r1[c0] = e;

    ab = fadd2(ab, v5); ab = ffma2(v0, NG2, ab);
    { ull nv = fmul2(v0, NG2); cd = ffma2(v5, v5, cd); cd = ffma2(nv, v0, cd); }
    e = fmaf(a1.y, b1.y, e); e = fmaf(-a0.x, b0.x, e);
    upk2(ab, fa, fb); upk2(cd, fc, fd);
    r4h[c1] = make_uint2(pkh2(fa, fb), pkh2(fc, fd)); r1[c1] = e;

    ab = fadd2(ab, v6); ab = ffma2(v1, NG2, ab);
    { ull nv = fmul2(v1, NG2); cd = ffma2(v6, v6, cd); cd = ffma2(nv, v1, cd); }
    e = fmaf(a1.z, b1.z, e); e = fmaf(-a0.y, b0.y, e);
    upk2(ab, fa, fb); upk2(cd, fc, fd);
    r4h[c2] = make_uint2(pkh2(fa, fb), pkh2(fc, fd)); r1[c2] = e;

    ab = fadd2(ab, v7); ab = ffma2(v2, NG2, ab);
    { ull nv = fmul2(v2, NG2); cd = ffma2(v7, v7, cd); cd = ffma2(nv, v2, cd); }
    e = fmaf(a1.w, b1.w, e); e = fmaf(-a0.z, b0.z, e);
    upk2(ab, fa, fb); upk2(cd, fc, fd);
    r4h[c3] = make_uint2(pkh2(fa, fb), pkh2(fc, fd)); r1[c3] = e;
}

// ---- H-pass + D-ring + emit for one slice (2 output rows per thread) ----
// ABCD row-sums in HADD2 (half2); converted to f32x2 once per slice result.
// E path and the D-ring stay fp32.
__device__ __forceinline__ void h_slice(
    const uint2* R4, const float* R1, int row0, int swc, int k,
    ull (&rAB)[2][5], ull (&rCD)[2][5], float (&rE)[2][5],
    ull (&tAB)[2], ull (&tCD)[2], float (&tE)[2],
    bool em, float& lcc)
{
    uint2 q0 = R4[(row0 + 0) * RROWH + swc]; float e0 = R1[(row0 + 0) * RROW + swc];
    uint2 q1 = R4[(row0 + 1) * RROWH + swc]; float e1 = R1[(row0 + 1) * RROW + swc];
    uint2 q2 = R4[(row0 + 2) * RROWH + swc]; float e2 = R1[(row0 + 2) * RROW + swc];
    uint2 q3 = R4[(row0 + 3) * RROWH + swc]; float e3 = R1[(row0 + 3) * RROW + swc];
    uint2 q4 = R4[(row0 + 4) * RROWH + swc]; float e4 = R1[(row0 + 4) * RROW + swc];
    uint2 q5 = R4[(row0 + 5) * RROWH + swc]; float e5 = R1[(row0 + 5) * RROW + swc];

    unsigned mab = hadd2u(hadd2u(q1.x, q2.x), hadd2u(q3.x, q4.x));
    unsigned mcd = hadd2u(hadd2u(q1.y, q2.y), hadd2u(q3.y, q4.y));
    float mE = (e1 + e2) + (e3 + e4);

    ull sAB0 = h2f2(hadd2u(mab, q0.x));
    ull sAB1 = h2f2(hadd2u(mab, q5.x));
    ull sCD0 = h2f2(hadd2u(mcd, q0.y));
    ull sCD1 = h2f2(hadd2u(mcd, q5.y));
    float sE0 = mE + e0, sE1 = mE + e5;

    tAB[0] = ffma2(rAB[0][k], NG2, fadd2(tAB[0], sAB0)); rAB[0][k] = sAB0;
    tCD[0] = ffma2(rCD[0][k], NG2, fadd2(tCD[0], sCD0)); rCD[0][k] = sCD0;
    tE[0] += sE0 - rE[0][k]; rE[0][k] = sE0;

    tAB[1] = ffma2(rAB[1][k], NG2, fadd2(tAB[1], sAB1)); rAB[1][k] = sAB1;
    tCD[1] = ffma2(rCD[1][k], NG2, fadd2(tCD[1], sCD1)); rCD[1][k] = sCD1;
    tE[1] += sE1 - rE[1][k]; rE[1][k] = sE1;

    if (em) {
        #pragma unroll
        for (int r = 0; r < 2; ++r) {
            float a, b, c, d;
            upk2(tAB[r], a, b);
            upk2(tCD[r], c, d);
            float ai = a * VINV;
            float bi = b * VINV;
            float cross = fmaf(-ai, b, tE[r]);
            float Ivar  = fmaf(-ai, a, c);
            float Jvar  = fmaf(-bi, b, d);
            lcc += __fdividef(cross * cross, fmaf(Ivar, Jvar, EPSV));
        }
    }
}

__global__ __launch_bounds__(NTHREADS, 2)
void ncc_main_kernel(const float* __restrict__ I, const float* __restrict__ J,
                     float* __restrict__ out) {
    extern __shared__ __align__(16) char dynsm[];   // [pair ring | rs4h | rs1 | redbuf]
    uint2* RS4H = reinterpret_cast<uint2*>(dynsm + RS4H_OFF);  // [2][40][RROWH]
    float* RS1  = reinterpret_cast<float*>(dynsm + RS1_OFF);   // [2][40][RROW]
    float* redbuf = reinterpret_cast<float*>(dynsm + RED_OFF);

    const int tid = threadIdx.x;
    const int tx = tid & 31;
    const int ty = tid >> 5;                 // 0..7 -> output rows 2ty, 2ty+1
    const int w0b = blockIdx.x * TILE_W;
    const int h0b = blockIdx.y * TILE_H;
    const int n   = blockIdx.z >> 1;
    const int z0  = (blockIdx.z & 1) * CHUNK;

    const float* __restrict__ Ibase = I + (size_t)n * DD * HW;
    const float* __restrict__ Jbase = J + (size_t)n * DD * HW;

    unsigned dynu32;
    asm("{ .reg .u64 t; cvta.to.shared.u64 t, %1; cvt.u32.u64 %0, t; }"
        : "=r"(dynu32) : "l"(dynsm));

    // ---- staging mapping: 8B chunks; 720 per slice, 3 per thread (3rd guarded) ----
    int  goff[3];
    unsigned soff[3];
    bool pfl[3];
    #pragma unroll
    for (int t = 0; t < 3; ++t) {
        int e = tid + t * NTHREADS;
        int pl = (e >= SL_CHUNKS) ? 1 : 0;
        int r = e - pl * SL_CHUNKS;
        int hh = r / CHUNKS_PER_SLICE, cc = r - hh * CHUNKS_PER_SLICE;
        int gh = h0b - 2 + hh;
        int gw = w0b - 2 + 2 * cc;
        bool inb = (e < SL_CHUNKS2) && (gh >= 0 && gh < HH) && (gw >= 0 && gw < WW - 1);
        goff[t] = inb ? (gh * WW + gw) : -1;
        soff[t] = (unsigned)(pl * PLANE_BYTES + hh * ROW_BYTES + 8 * cc);
        pfl[t] = (pl != 0);
    }
    const bool has3 = (tid < SL_CHUNKS2 - 2 * NTHREADS);   // tid < 208

    // ---- W-pass task mapping: 320 tasks/pair; t1 = tid, t2 = 256+tid (tid<64) ----
    int s1 = (tid >= 160) ? 1 : 0;
    int r1i = tid - 160 * s1;
    int whh1 = r1i >> 3, wwg1 = r1i & 7;
    const int oIJ1 = s1 * SLICE_BYTES + whh1 * ROW_BYTES + wwg1 * 16;
    const int rsrow1 = s1 * HALO_H + whh1;
    const int c10 = wwg1, c11 = 8 + (wwg1 ^ 2), c12 = 16 + (wwg1 ^ 4), c13 = 24 + (wwg1 ^ 6);

    int r2i = tid + 96;                       // slice 1, rows 12..19 (tid<64)
    int whh2 = r2i >> 3, wwg2 = r2i & 7;
    const int oIJ2 = SLICE_BYTES + whh2 * ROW_BYTES + wwg2 * 16;
    const int rsrow2 = HALO_H + whh2;
    const int c20 = wwg2, c21 = 8 + (wwg2 ^ 2), c22 = 16 + (wwg2 ^ 4), c23 = 24 + (wwg2 ^ 6);

    // ---- H-pass read column (inverse of store swizzle, logical w = tx) ----
    const int swc = 8 * (tx & 3) + ((tx >> 2) ^ (2 * (tx & 3)));

    // ---- pipeline state ----
    ull rAB[2][5] = {{0,0,0,0,0},{0,0,0,0,0}};
    ull rCD[2][5] = {{0,0,0,0,0},{0,0,0,0,0}};
    float rE[2][5] = {{0,0,0,0,0},{0,0,0,0,0}};
    ull tAB[2] = {0, 0}, tCD[2] = {0, 0};
    float tE[2] = {0.f, 0.f};
    float local_cc = 0.f;

    // ---- async stage of one pair (slices m0, m0+1) into ring buffer at dstoff ----
    auto issue_pair = [&](int m0, unsigned dstoff) {
        #pragma unroll
        for (int s = 0; s < 2; ++s) {
            int z = z0 - 2 + m0 + s;
            bool zv = ((unsigned)z < (unsigned)DD);
            int zc = zv ? z : 0;
            const float* pi = Ibase + (size_t)zc * HW;
            const float* pj = Jbase + (size_t)zc * HW;
            unsigned db = dynu32 + dstoff + (unsigned)(s * SLICE_BYTES);
            #pragma unroll
            for (int t = 0; t < 3; ++t) {
                if (t < 2 || has3) {
                    int go = goff[t];
                    unsigned sz = (zv && go >= 0) ? 8u : 0u;
                    int g2 = (go >= 0) ? go : 0;
                    const float* src = (pfl[t] ? pj : pi) + g2;
                    cpa8(db + soff[t], src, sz);
                }
            }
        }
        asm volatile("cp.async.commit_group;" ::: "memory");
    };

    // prologue: pair1 (slices 0,1) -> buf0, pair2 (slices 2,3) -> buf1
    issue_pair(0, 0u);
    issue_pair(2, (unsigned)PAIR_BYTES);
    unsigned offW = 0u, offN = PAIR_BYTES, offI = 2u * PAIR_BYTES;

    constexpr int K1[5] = {3, 0, 2, 4, 1};   // (2j+3)%5
    constexpr int K2[5] = {4, 1, 3, 0, 2};   // (2j+4)%5

    for (int g = 0; g < 9; ++g) {
        #pragma unroll
        for (int j = 0; j < 5; ++j) {
            const int p = 1 + 5 * g + j;
            const int pb = p & 1, wb = pb ^ 1;

            asm volatile("cp.async.wait_group 1;" ::: "memory");
            __syncthreads();     // pair p staged in offW; rs[pb] final; rs[wb] free

            // issue stage of pair p+2 (slices 2p+2, 2p+3) into free buffer
            issue_pair(2 * p + 2, offI);

            // ---- W-pass on pair p (slices 2p-2, 2p-1) -> rs[wb] ----
            if (p <= 42) {
                const char* base = dynsm + offW;
                w_task(base + oIJ1,
                       RS4H + (wb * RS_ROWS + rsrow1) * RROWH,
                       RS1  + (wb * RS_ROWS + rsrow1) * RROW,
                       c10, c11, c12, c13);
                if (tid < 64)
                    w_task(base + oIJ2,
                           RS4H + (wb * RS_ROWS + rsrow2) * RROWH,
                           RS1  + (wb * RS_ROWS + rsrow2) * RROW,
                           c20, c21, c22, c23);
            }

            // ---- H-pass on pair p-1 (slices m=2p-4, 2p-3) from rs[pb] ----
            if (p >= 2 && p <= 43) {
                const bool em = (p >= 4);
                const uint2* R4b = RS4H + pb * RS_ROWS * RROWH;
                const float* R1b = RS1  + pb * RS_ROWS * RROW;
                h_slice(R4b, R1b, 2 * ty, swc, K1[j],
                        rAB, rCD, rE, tAB, tCD, tE, em, local_cc);
                h_slice(R4b + HALO_H * RROWH, R1b + HALO_H * RROW, 2 * ty, swc, K2[j],
                        rAB, rCD, rE, tAB, tCD, tE, em, local_cc);
            }

            unsigned t0 = offW; offW = offN; offN = offI; offI = t0;
        }
    }

    asm volatile("cp.async.wait_group 0;" ::: "memory");

    // ---- block reduction + fused finalize (last block writes out) ----
    float v = local_cc;
    #pragma unroll
    for (int off = 16; off > 0; off >>= 1)
        v += __shfl_xor_sync(0xFFFFFFFFu, v, off);
    __syncthreads();               // rs/red space free
    if (tx == 0) redbuf[ty] = v;
    __syncthreads();
    if (tid == 0) {
        float w = ((redbuf[0] + redbuf[1]) + (redbuf[2] + redbuf[3]))
                + ((redbuf[4] + redbuf[5]) + (redbuf[6] + redbuf[7]));
        atomicAdd(&g_acc, (double)w);
        __threadfence();
        unsigned t = atomicAdd(&g_cnt, 1u);
        if (t == NBLOCKS - 1) {
            double total = *((volatile double*)&g_acc);
            out[0] = (float)(-total / ((double)NN * DD * HH * WW));
            g_acc = 0.0;          // reset for next graph replay
            g_cnt = 0u;
        }
    }
}

extern "C" void kernel_launch(void* const* d_in, const int* in_sizes, int n_in,
                              void* d_out, int out_size) {
    const float* I = (const float*)d_in[0];
    const float* J = (const float*)d_in[1];
    float* out = (float*)d_out;

    // Opt in to >48KB combined shared memory (idempotent; non-stream host call,
    // legal during graph capture).
    cudaFuncSetAttribute(ncc_main_kernel,
                         cudaFuncAttributeMaxDynamicSharedMemorySize, DYN_TOTAL);

    dim3 block(NTHREADS);
    dim3 grid(WW / TILE_W, HH / TILE_H, NN * 2);   // 6 x 12 x 4 = 288 blocks
    ncc_main_kernel<<<grid, block, DYN_TOTAL>>>(I, J, out);
}